// round 14
// baseline (speedup 1.0000x reference)
#include <cuda_runtime.h>
#include <cuda_fp16.h>
#include <mma.h>
#include <math.h>
#include <stdint.h>

#define NA_  100000
#define NP_  200000
#define EW_  1000000
#define EWB_ 1000000
#define EC_  2000000
#define KP2_L1 144   // 128 + 16 (ones/bias column block)
#define KP2_L2 48    // 32 + 16

// ---------------- scratch (device globals; no allocation allowed) ----------
__device__ float g_qa[(NA_+128)*32], g_qp[(NP_+128)*32];
__device__ __align__(32) __half g_kv0[(NA_+128)*64];   // authors as src (writes)
__device__ __align__(32) __half g_kv1[(NP_+128)*64];   // papers as src (written_by)
__device__ __align__(32) __half g_kv2[(NP_+128)*64];   // papers as src (cites)
__device__ float g_xa[NA_*32], g_xp[NP_*32];
__device__ float g_h1a[NA_*32], g_h1p[NP_*32];
__device__ __align__(32) __half g_x16a[NA_*KP2_L1], g_x16p[NP_*KP2_L1];
// CSR per relation (dst-indexed)
__device__ int g_deg_w[NP_], g_rp_w[NP_+1];  __device__ int g_cs_w[EW_];
__device__ int g_deg_b[NA_], g_rp_b[NA_+1];  __device__ int g_cs_b[EWB_];
__device__ int g_deg_c[NP_], g_rp_c[NP_+1];  __device__ int g_cs_c[EC_];
__device__ int g_bs_w[256], g_bs_b[256], g_bs_c[256];
// degree-binned permutations (agg load balance)
__device__ int g_hist[128];           // [0..63] authors, [64..127] papers
__device__ int g_permA[NA_], g_permP[NP_];
// composite weights: 8 tasks x [32][KP2<=144] fp16 (col-major B, bias at row F)
__device__ __align__(32) __half g_Wt[8*32*KP2_L1];

// ---------------- helpers ---------------------------------------------------
__device__ __forceinline__ unsigned long long pack2(float lo, float hi) {
    unsigned long long r;
    asm("mov.b64 %0, {%1,%2};" : "=l"(r) : "f"(lo), "f"(hi));
    return r;
}
__device__ __forceinline__ void ffma2(unsigned long long& acc,
                                      unsigned long long a, unsigned long long b) {
    asm("fma.rn.f32x2 %0, %1, %2, %0;" : "+l"(acc) : "l"(a), "l"(b));
}
__device__ __forceinline__ float2 unpack2(unsigned long long v) {
    float2 r;
    asm("mov.b64 {%0,%1}, %2;" : "=f"(r.x), "=f"(r.y) : "l"(v));
    return r;
}
static inline int divup(int a, int b) { return (a + b - 1) / b; }

// ---------------- fused CSR build ----------------------------------------------
struct Rel3 {
    const int *e0, *e1, *e2;
    int E0, E1, E2;
    int n0, n1, n2;
    int *deg0, *deg1, *deg2;
    int *rp0, *rp1, *rp2;
    int *cs0, *cs1, *cs2;
    int *bs0, *bs1, *bs2;
};

__global__ void zero_all_kernel(Rel3 R) {
    int i = blockIdx.x * blockDim.x + threadIdx.x;
    int t = R.n0 + R.n1 + R.n2;
    if (i >= t) return;
    if (i < R.n0) R.deg0[i] = 0;
    else if (i < R.n0 + R.n1) R.deg1[i - R.n0] = 0;
    else R.deg2[i - R.n0 - R.n1] = 0;
}
__global__ void count_all_kernel(Rel3 R) {
    int i = blockIdx.x * blockDim.x + threadIdx.x;
    if (i < R.E0) { atomicAdd(&R.deg0[__ldg(R.e0 + R.E0 + i)], 1); return; }
    i -= R.E0;
    if (i < R.E1) { atomicAdd(&R.deg1[__ldg(R.e1 + R.E1 + i)], 1); return; }
    i -= R.E1;
    if (i < R.E2) { atomicAdd(&R.deg2[__ldg(R.e2 + R.E2 + i)], 1); }
}
__device__ __forceinline__ void rel_sel(const Rel3& R, int r, const int*& deg, int& n, int*& bsum) {
    if (r == 0) { deg = R.deg0; n = R.n0; bsum = R.bs0; }
    else if (r == 1) { deg = R.deg1; n = R.n1; bsum = R.bs1; }
    else { deg = R.deg2; n = R.n2; bsum = R.bs2; }
}
__global__ void scan_p1_all(Rel3 R) {
    const int* deg; int n; int* bsum;
    rel_sel(R, blockIdx.y, deg, n, bsum);
    int base = blockIdx.x * 1024;
    if (base >= n) return;
    __shared__ int sm[256];
    int t = threadIdx.x;
    int s = 0;
#pragma unroll
    for (int j = 0; j < 4; j++) {
        int i = base + t * 4 + j;
        if (i < n) s += deg[i];
    }
    sm[t] = s; __syncthreads();
#pragma unroll
    for (int o = 128; o > 0; o >>= 1) {
        if (t < o) sm[t] += sm[t + o];
        __syncthreads();
    }
    if (t == 0) bsum[blockIdx.x] = sm[0];
}
__global__ void scan_p2_all(Rel3 R) {
    const int* degc; int n; int* bsum;
    rel_sel(R, blockIdx.x, degc, n, bsum);
    int* rp_last = (blockIdx.x == 0 ? R.rp0 : blockIdx.x == 1 ? R.rp1 : R.rp2) + n;
    int nb = (n + 1023) / 1024;
    __shared__ int sm[256];
    int t = threadIdx.x;
    int v = (t < nb) ? bsum[t] : 0;
    sm[t] = v; __syncthreads();
    for (int o = 1; o < 256; o <<= 1) {
        int x = (t >= o) ? sm[t - o] : 0;
        __syncthreads();
        sm[t] += x;
        __syncthreads();
    }
    if (t < nb) bsum[t] = sm[t] - v;
    if (t == 255) *rp_last = sm[255];
}
__global__ void scan_p3_all(Rel3 R) {
    const int* deg; int n; int* bsum;
    rel_sel(R, blockIdx.y, deg, n, bsum);
    int* rp  = (blockIdx.y == 0 ? R.rp0  : blockIdx.y == 1 ? R.rp1  : R.rp2);
    int* cur = (blockIdx.y == 0 ? R.deg0 : blockIdx.y == 1 ? R.deg1 : R.deg2);
    int base = blockIdx.x * 1024;
    if (base >= n) return;
    __shared__ int sm[256];
    int t = threadIdx.x;
    int v[4]; int s = 0;
#pragma unroll
    for (int j = 0; j < 4; j++) {
        int i = base + t * 4 + j;
        v[j] = (i < n) ? deg[i] : 0;
        s += v[j];
    }
    sm[t] = s; __syncthreads();
    for (int o = 1; o < 256; o <<= 1) {
        int x = (t >= o) ? sm[t - o] : 0;
        __syncthreads();
        sm[t] += x;
        __syncthreads();
    }
    int run = bsum[blockIdx.x] + sm[t] - s;
#pragma unroll
    for (int j = 0; j < 4; j++) {
        int i = base + t * 4 + j;
        if (i < n) { rp[i] = run; cur[i] = run; }
        run += v[j];
    }
}
__global__ void scatter_all_kernel(Rel3 R) {
    int i = blockIdx.x * blockDim.x + threadIdx.x;
    const int* e; int E; int* cur; int* cs;
    if (i < R.E0) { e = R.e0; E = R.E0; cur = R.deg0; cs = R.cs0; }
    else {
        i -= R.E0;
        if (i < R.E1) { e = R.e1; E = R.E1; cur = R.deg1; cs = R.cs1; }
        else {
            i -= R.E1;
            if (i >= R.E2) return;
            e = R.e2; E = R.E2; cur = R.deg2; cs = R.cs2;
        }
    }
    int slot = atomicAdd(&cur[__ldg(e + E + i)], 1);
    cs[slot] = __ldg(e + i);
}

// ---------------- degree-binned permutation (agg load balance) ------------------
// bin = per-warp loop iteration count (unroll-4 granularity), clamped to 63.
__global__ void zero_hist_kernel(int* __restrict__ hist) {
    if (threadIdx.x < 128) hist[threadIdx.x] = 0;
}
__device__ __forceinline__ int bin_author(const int* rpb, int i) {
    int db = __ldg(rpb + i + 1) - __ldg(rpb + i);
    return min(63, (db + 3) >> 2);
}
__device__ __forceinline__ int bin_paper(const int* rpw, const int* rpc, int i) {
    int dw = __ldg(rpw + i + 1) - __ldg(rpw + i);
    int dc = __ldg(rpc + i + 1) - __ldg(rpc + i);
    return min(63, ((dw + 3) >> 2) + ((dc + 3) >> 2));
}
__global__ void key_count_kernel(const int* __restrict__ rpb,
                                 const int* __restrict__ rpw, const int* __restrict__ rpc,
                                 int* __restrict__ hist) {
    int i = blockIdx.x * blockDim.x + threadIdx.x;
    if (i < NA_) {
        atomicAdd(&hist[bin_author(rpb, i)], 1);
    } else if (i < NA_ + NP_) {
        int p = i - NA_;
        atomicAdd(&hist[64 + bin_paper(rpw, rpc, p)], 1);
    }
}
__global__ void hist_scan_kernel(int* __restrict__ hist) {
    __shared__ int sm[128];
    int t = threadIdx.x;
    int v = hist[t];
    sm[t] = v; __syncthreads();
    for (int o = 1; o < 64; o <<= 1) {
        int add = ((t & 63) >= o) ? sm[t - o] : 0;
        __syncthreads();
        sm[t] += add;
        __syncthreads();
    }
    hist[t] = sm[t] - v;   // exclusive within each 64-bin half
}
__global__ void perm_scatter_kernel(const int* __restrict__ rpb,
                                    const int* __restrict__ rpw, const int* __restrict__ rpc,
                                    int* __restrict__ hist,
                                    int* __restrict__ permA, int* __restrict__ permP) {
    int i = blockIdx.x * blockDim.x + threadIdx.x;
    if (i < NA_) {
        int slot = atomicAdd(&hist[bin_author(rpb, i)], 1);
        permA[slot] = i;
    } else if (i < NA_ + NP_) {
        int p = i - NA_;
        int slot = atomicAdd(&hist[64 + bin_paper(rpw, rpc, p)], 1);
        permP[slot] = p;
    }
}

// ---------------- weight composition (all 8 tasks, one launch) -----------------
struct CTask { const float* W; const float* b; const float* T; int prel_idx; };
struct CArgs { CTask t[8]; const float* prel; };

__global__ void compose_all_kernel(CArgs args, int F, int KP2, __half* __restrict__ Wt) {
    int task = blockIdx.y;
    int gw   = (blockIdx.x * blockDim.x + threadIdx.x) >> 5;
    int lane = threadIdx.x & 31;
    if (gw >= KP2) return;
    CTask tk = args.t[task];
    __half* dst = &Wt[((size_t)task * 32 + lane) * KP2 + gw];
    if (gw > F) { *dst = __float2half(0.f); return; }
    float scale = (tk.prel_idx >= 0) ? (__ldg(args.prel + tk.prel_idx) * 0.17677669529663687f) : 1.0f;
    float rv = (gw == F) ? tk.b[lane] : tk.W[(size_t)gw * 32 + lane];
    float acc;
    if (tk.T) {
        acc = 0.f;
#pragma unroll
        for (int j = 0; j < 32; j++) {
            float rj = __shfl_sync(0xffffffffu, rv, j);
            acc = fmaf(rj, __ldg(tk.T + j * 32 + lane), acc);
        }
    } else acc = rv;
    *dst = __float2half(acc * scale);
}

// ---------------- fp32 -> fp16 conversion with ones column ----------------------
__global__ void cvt16_kernel(const float* __restrict__ x, __half* __restrict__ y,
                             int n, int F, int KP2) {
    int i = blockIdx.x * blockDim.x + threadIdx.x;
    int cpr = KP2 >> 2;
    int total = n * cpr;
    if (i >= total) return;
    int node = i / cpr;
    int c4 = (i % cpr) << 2;
    float4 v = make_float4(0.f, 0.f, 0.f, 0.f);
    if (c4 < F)       v = __ldg((const float4*)(x + (size_t)node * F + c4));
    else if (c4 == F) v.x = 1.0f;
    __half2 h0 = __floats2half2_rn(v.x, v.y);
    __half2 h1 = __floats2half2_rn(v.z, v.w);
    __half2* dst = (__half2*)(y + (size_t)node * KP2 + c4);
    dst[0] = h0; dst[1] = h1;
}

// ---------------- wmma (HMMA) projection — direct-store, bias-folded ------------
template<int KP2, int NMAT>
__global__ void __launch_bounds__(256) proj_wmma_kernel(
        const __half* __restrict__ x16, const __half* __restrict__ Wt,
        float* __restrict__ qout,
        __half* __restrict__ o1, __half* __restrict__ o2,
        __half* __restrict__ o3, __half* __restrict__ o4, int n) {
    extern __shared__ __align__(32) __half smem_h[];
    const int LD = KP2 + 8;
    __half* sB = smem_h;
    __half* sA = sB + NMAT * 32 * LD;
    int tid = threadIdx.x, wid = tid >> 5;
    int base = blockIdx.x * 128;
    const int CH = KP2 / 8;
    for (int idx = tid; idx < NMAT * 32 * CH; idx += 256) {
        int r = idx / CH, c8 = (idx % CH) * 8;
        *(uint4*)(sB + r * LD + c8) = *(const uint4*)(Wt + (size_t)r * KP2 + c8);
    }
    for (int idx = tid; idx < 128 * CH; idx += 256) {
        int row = idx / CH, c8 = (idx % CH) * 8;
        uint4 v = make_uint4(0, 0, 0, 0);
        if (base + row < n) v = *(const uint4*)(x16 + (size_t)(base + row) * KP2 + c8);
        *(uint4*)(sA + row * LD + c8) = v;
    }
    __syncthreads();

    using namespace nvcuda;
    int m0 = wid * 16;
    int node0 = base + m0;
    wmma::fragment<wmma::accumulator, 16, 16, 16, float> q0f, q1f;
    wmma::fill_fragment(q0f, 0.f);
    wmma::fill_fragment(q1f, 0.f);
    wmma::fragment<wmma::accumulator, 16, 16, 16, __half> ah[NMAT-1][2];
#pragma unroll
    for (int m = 0; m < NMAT-1; m++) {
        wmma::fill_fragment(ah[m][0], __float2half(0.f));
        wmma::fill_fragment(ah[m][1], __float2half(0.f));
    }

#pragma unroll
    for (int k0 = 0; k0 < KP2; k0 += 16) {
        wmma::fragment<wmma::matrix_a, 16, 16, 16, __half, wmma::row_major> fa;
        wmma::load_matrix_sync(fa, sA + m0 * LD + k0, LD);
        {
            wmma::fragment<wmma::matrix_b, 16, 16, 16, __half, wmma::col_major> fb0, fb1;
            wmma::load_matrix_sync(fb0, sB + k0, LD);
            wmma::load_matrix_sync(fb1, sB + 16 * LD + k0, LD);
            wmma::mma_sync(q0f, fa, fb0, q0f);
            wmma::mma_sync(q1f, fa, fb1, q1f);
        }
#pragma unroll
        for (int m = 1; m < NMAT; m++) {
            wmma::fragment<wmma::matrix_b, 16, 16, 16, __half, wmma::col_major> fb0, fb1;
            const __half* Bm = sB + m * 32 * LD;
            wmma::load_matrix_sync(fb0, Bm + k0, LD);
            wmma::load_matrix_sync(fb1, Bm + 16 * LD + k0, LD);
            wmma::mma_sync(ah[m-1][0], fa, fb0, ah[m-1][0]);
            wmma::mma_sync(ah[m-1][1], fa, fb1, ah[m-1][1]);
        }
    }
    wmma::store_matrix_sync(qout + (size_t)node0 * 32,      q0f, 32, wmma::mem_row_major);
    wmma::store_matrix_sync(qout + (size_t)node0 * 32 + 16, q1f, 32, wmma::mem_row_major);
    __half* outs[4] = {o1, o2, o3, o4};
#pragma unroll
    for (int m = 1; m < NMAT; m++) {
        wmma::store_matrix_sync(outs[m-1] + (size_t)node0 * 64,      ah[m-1][0], 64, wmma::mem_row_major);
        wmma::store_matrix_sync(outs[m-1] + (size_t)node0 * 64 + 16, ah[m-1][1], 64, wmma::mem_row_major);
    }
}
template<int KP2, int NMAT>
static constexpr int proj_smem() {
    return (NMAT*32 + 128) * (KP2+8) * 2;
}

// ---------------- dst-centric edge aggregation (8 dst/warp, degree-binned) ------
__device__ __forceinline__ float edge_score(const uint4& kh, const float4& q0, const float4& q1) {
    float2 k0 = __half22float2(*(const __half2*)&kh.x);
    float2 k1 = __half22float2(*(const __half2*)&kh.y);
    float2 k2 = __half22float2(*(const __half2*)&kh.z);
    float2 k3 = __half22float2(*(const __half2*)&kh.w);
    return q0.x*k0.x + q0.y*k0.y + q0.z*k1.x + q0.w*k1.y
         + q1.x*k2.x + q1.y*k2.y + q1.z*k3.x + q1.w*k3.y;
}
__device__ __forceinline__ void edge_accum(unsigned long long acc[4], const uint4& vh, float ex) {
    unsigned long long ex2 = pack2(ex, ex);
    float2 v0 = __half22float2(*(const __half2*)&vh.x);
    float2 v1 = __half22float2(*(const __half2*)&vh.y);
    float2 v2 = __half22float2(*(const __half2*)&vh.z);
    float2 v3 = __half22float2(*(const __half2*)&vh.w);
    ffma2(acc[0], pack2(v0.x, v0.y), ex2);
    ffma2(acc[1], pack2(v1.x, v1.y), ex2);
    ffma2(acc[2], pack2(v2.x, v2.y), ex2);
    ffma2(acc[3], pack2(v3.x, v3.y), ex2);
}
__device__ __forceinline__ float accum_rel_h(int b0, int b1, const int* __restrict__ cs,
                                             const __half* __restrict__ kv,
                                             const float4& q0, const float4& q1,
                                             unsigned gmask, int ql,
                                             unsigned long long acc[4]) {
    float den = 0.f;
    int e = b0;
    for (; e + 4 <= b1; e += 4) {
        int s0 = __ldg(cs + e);
        int s1 = __ldg(cs + e + 1);
        int s2 = __ldg(cs + e + 2);
        int s3 = __ldg(cs + e + 3);
        const uint4* r0 = (const uint4*)(kv + (size_t)s0 * 64);
        const uint4* r1 = (const uint4*)(kv + (size_t)s1 * 64);
        const uint4* r2 = (const uint4*)(kv + (size_t)s2 * 64);
        const uint4* r3 = (const uint4*)(kv + (size_t)s3 * 64);
        uint4 k0 = __ldg(r0 + ql),     k1 = __ldg(r1 + ql);
        uint4 k2 = __ldg(r2 + ql),     k3 = __ldg(r3 + ql);
        uint4 v0 = __ldg(r0 + 4 + ql), v1 = __ldg(r1 + 4 + ql);
        uint4 v2 = __ldg(r2 + 4 + ql), v3 = __ldg(r3 + 4 + ql);
        float sc0 = edge_score(k0, q0, q1);
        float sc1 = edge_score(k1, q0, q1);
        float sc2 = edge_score(k2, q0, q1);
        float sc3 = edge_score(k3, q0, q1);
        sc0 += __shfl_xor_sync(gmask, sc0, 1);
        sc1 += __shfl_xor_sync(gmask, sc1, 1);
        sc2 += __shfl_xor_sync(gmask, sc2, 1);
        sc3 += __shfl_xor_sync(gmask, sc3, 1);
        sc0 += __shfl_xor_sync(gmask, sc0, 2);
        sc1 += __shfl_xor_sync(gmask, sc1, 2);
        sc2 += __shfl_xor_sync(gmask, sc2, 2);
        sc3 += __shfl_xor_sync(gmask, sc3, 2);
        float ex0 = __expf(fminf(sc0, 60.0f));
        float ex1 = __expf(fminf(sc1, 60.0f));
        float ex2 = __expf(fminf(sc2, 60.0f));
        float ex3 = __expf(fminf(sc3, 60.0f));
        edge_accum(acc, v0, ex0);
        edge_accum(acc, v1, ex1);
        edge_accum(acc, v2, ex2);
        edge_accum(acc, v3, ex3);
        den += (ex0 + ex1) + (ex2 + ex3);
    }
    for (; e < b1; e++) {
        int s0 = __ldg(cs + e);
        const uint4* r0 = (const uint4*)(kv + (size_t)s0 * 64);
        uint4 k0 = __ldg(r0 + ql);
        uint4 v0 = __ldg(r0 + 4 + ql);
        float sc0 = edge_score(k0, q0, q1);
        sc0 += __shfl_xor_sync(gmask, sc0, 1);
        sc0 += __shfl_xor_sync(gmask, sc0, 2);
        float ex0 = __expf(fminf(sc0, 60.0f));
        edge_accum(acc, v0, ex0);
        den += ex0;
    }
    return den;
}
__global__ void agg1_kernel(const int* __restrict__ perm,
                            const int* __restrict__ rp, const int* __restrict__ cs,
                            const float* __restrict__ q, const __half* __restrict__ kv,
                            float* __restrict__ xout, int n) {
    int gw   = (blockIdx.x * blockDim.x + threadIdx.x) >> 5;
    int lane = threadIdx.x & 31;
    int sub  = lane >> 2;
    int ql   = lane & 3;
    unsigned gmask = 0xFu << (sub * 4);
    int draw = gw * 8 + sub;
    bool valid = (draw < n);
    int d = __ldg(perm + (valid ? draw : (n - 1)));
    int b0 = __ldg(rp + d);
    int b1 = valid ? __ldg(rp + d + 1) : b0;
    float4 q0 = __ldg((const float4*)(q + (size_t)d * 32) + ql * 2);
    float4 q1 = __ldg((const float4*)(q + (size_t)d * 32) + ql * 2 + 1);
    unsigned long long acc[4];
    acc[0] = acc[1] = acc[2] = acc[3] = pack2(0.f, 0.f);
    float den = accum_rel_h(b0, b1, cs, kv, q0, q1, gmask, ql, acc);
    if (valid) {
        float inv = (den > 0.f) ? (1.0f / den) : 0.0f;
        float2 a0 = unpack2(acc[0]), a1 = unpack2(acc[1]);
        float2 a2 = unpack2(acc[2]), a3 = unpack2(acc[3]);
        *((float4*)(xout + (size_t)d * 32) + ql * 2)     = make_float4(a0.x*inv, a0.y*inv, a1.x*inv, a1.y*inv);
        *((float4*)(xout + (size_t)d * 32) + ql * 2 + 1) = make_float4(a2.x*inv, a2.y*inv, a3.x*inv, a3.y*inv);
    }
}
__global__ void agg2_kernel(const int* __restrict__ perm,
                            const int* __restrict__ rp1, const int* __restrict__ cs1,
                            const __half* __restrict__ kvA,
                            const int* __restrict__ rp2, const int* __restrict__ cs2,
                            const __half* __restrict__ kvB,
                            const float* __restrict__ q,
                            float* __restrict__ xout, int n) {
    int gw   = (blockIdx.x * blockDim.x + threadIdx.x) >> 5;
    int lane = threadIdx.x & 31;
    int sub  = lane >> 2;
    int ql   = lane & 3;
    unsigned gmask = 0xFu << (sub * 4);
    int draw = gw * 8 + sub;
    bool valid = (draw < n);
    int d = __ldg(perm + (valid ? draw : (n - 1)));
    float4 q0 = __ldg((const float4*)(q + (size_t)d * 32) + ql * 2);
    float4 q1 = __ldg((const float4*)(q + (size_t)d * 32) + ql * 2 + 1);
    int a0 = __ldg(rp1 + d);
    int a1 = valid ? __ldg(rp1 + d + 1) : a0;
    int c0 = __ldg(rp2 + d);
    int c1 = valid ? __ldg(rp2 + d + 1) : c0;
    unsigned long long accA[4], accB[4];
    accA[0]=accA[1]=accA[2]=accA[3]=pack2(0.f,0.f);
    accB[0]=accB[1]=accB[2]=accB[3]=pack2(0.f,0.f);
    float denA = accum_rel_h(a0, a1, cs1, kvA, q0, q1, gmask, ql, accA);
    float denB = accum_rel_h(c0, c1, cs2, kvB, q0, q1, gmask, ql, accB);
    if (valid) {
        float invA = (denA > 0.f) ? (1.0f / denA) : 0.0f;
        float invB = (denB > 0.f) ? (1.0f / denB) : 0.0f;
        float2 rA[4], rB[4];
#pragma unroll
        for (int i = 0; i < 4; i++) { rA[i] = unpack2(accA[i]); rB[i] = unpack2(accB[i]); }
        *((float4*)(xout + (size_t)d * 32) + ql * 2) =
            make_float4(rA[0].x*invA + rB[0].x*invB, rA[0].y*invA + rB[0].y*invB,
                        rA[1].x*invA + rB[1].x*invB, rA[1].y*invA + rB[1].y*invB);
        *((float4*)(xout + (size_t)d * 32) + ql * 2 + 1) =
            make_float4(rA[2].x*invA + rB[2].x*invB, rA[2].y*invA + rB[2].y*invB,
                        rA[3].x*invA + rB[3].x*invB, rA[3].y*invA + rB[3].y*invB);
    }
}

// ---------------- output transform ---------------------------------------------
__global__ void out_kernel(const float* __restrict__ x1,
                           const float* __restrict__ Wa, const float* __restrict__ ba,
                           const float* __restrict__ skipv, int t_idx,
                           const float* __restrict__ xin,
                           float* __restrict__ out, __half* __restrict__ out16,
                           int n, int use_skip) {
    __shared__ float sW[1024];
    for (int i = threadIdx.x; i < 1024; i += blockDim.x) sW[i] = Wa[i];
    __syncthreads();
    int lane = threadIdx.x & 31;
    int gw = blockIdx.x * (blockDim.x >> 5) + (threadIdx.x >> 5);
    int n0 = gw * 4;
    if (n0 >= n) return;
    int m = n - n0; if (m > 4) m = 4;

    float4 xr[4];
#pragma unroll
    for (int j = 0; j < 4; j++) {
        if (j < m && lane < 8) {
            float4 a = __ldg((const float4*)(x1 + (size_t)(n0 + j) * 32) + lane);
            a.x = 0.5f * a.x * (1.0f + erff(a.x * 0.7071067811865475f));
            a.y = 0.5f * a.y * (1.0f + erff(a.y * 0.7071067811865475f));
            a.z = 0.5f * a.z * (1.0f + erff(a.z * 0.7071067811865475f));
            a.w = 0.5f * a.w * (1.0f + erff(a.w * 0.7071067811865475f));
            xr[j] = a;
        } else {
            xr[j] = make_float4(0.f, 0.f, 0.f, 0.f);
        }
    }
    unsigned long long A01 = pack2(ba[lane], ba[lane]), A23 = A01;
    for (int i0 = 0; i0 < 32; i0 += 4) {
        int sl = i0 >> 2;
        float xs[4][4];
#pragma unroll
        for (int j = 0; j < 4; j++) {
            xs[j][0] = __shfl_sync(0xffffffffu, xr[j].x, sl);
            xs[j][1] = __shfl_sync(0xffffffffu, xr[j].y, sl);
            xs[j][2] = __shfl_sync(0xffffffffu, xr[j].z, sl);
            xs[j][3] = __shfl_sync(0xffffffffu, xr[j].w, sl);
        }
#pragma unroll
        for (int c = 0; c < 4; c++) {
            float w = sW[(i0 + c) * 32 + lane];
            unsigned long long w2 = pack2(w, w);
            ffma2(A01, pack2(xs[0][c], xs[1][c]), w2);
            ffma2(A23, pack2(xs[2][c], xs[3][c]), w2);
        }
    }
    float2 a01 = unpack2(A01), a23 = unpack2(A23);
    float o[4] = {a01.x, a01.y, a23.x, a23.y};
    if (use_skip) {
        float a = 1.0f / (1.0f + expf(-__ldg(skipv + t_idx)));
#pragma unroll
        for (int j = 0; j < 4; j++) {
            if (j < m)
                o[j] = a * o[j] + (1.0f - a) * __ldg(xin + (size_t)(n0 + j) * 32 + lane);
        }
    }
#pragma unroll
    for (int j = 0; j < 4; j++) {
        if (j < m) {
            out[(size_t)(n0 + j) * 32 + lane] = o[j];
            if (out16) {
                out16[(size_t)(n0 + j) * KP2_L2 + lane] = __float2half(o[j]);
                if (lane < 16)
                    out16[(size_t)(n0 + j) * KP2_L2 + 32 + lane] =
                        __float2half(lane == 0 ? 1.0f : 0.0f);
            }
        }
    }
}

// ---------------- host orchestration ----------------------------------------
struct LayerW {
    const float *Wk, *bk, *Wq, *bq, *Wv, *bv, *Wa, *ba, *skip, *arel, *mrel, *prel;
};

template<int KP2>
static void run_proj(const __half* x16a, const __half* x16p, int F,
                     const LayerW& L,
                     float* qa, float* qp,
                     __half* kv0, __half* kv1, __half* kv2,
                     __half* Wt) {
    const int BT = 256;
    int wsz = F * 32;
    CArgs ca;
    ca.prel = L.prel;
    ca.t[0] = { L.Wq,       L.bq,      (const float*)0, -1 };
    ca.t[1] = { L.Wk,       L.bk,      L.arel + 0,      0  };
    ca.t[2] = { L.Wv,       L.bv,      L.mrel + 0,      -1 };
    ca.t[3] = { L.Wq + wsz, L.bq + 32, (const float*)0, -1 };
    ca.t[4] = { L.Wk + wsz, L.bk + 32, L.arel + 1024,   1  };
    ca.t[5] = { L.Wv + wsz, L.bv + 32, L.mrel + 1024,   -1 };
    ca.t[6] = { L.Wk + wsz, L.bk + 32, L.arel + 2048,   2  };
    ca.t[7] = { L.Wv + wsz, L.bv + 32, L.mrel + 2048,   -1 };
    dim3 cg(divup(KP2 * 32, BT), 8);
    compose_all_kernel<<<cg, BT>>>(ca, F, KP2, Wt);

    proj_wmma_kernel<KP2, 5><<<divup(NP_, 128), 256, proj_smem<KP2,5>()>>>(
        x16p, Wt + (size_t)3 * 32 * KP2, qp,
        kv1, kv1 + 32, kv2, kv2 + 32, NP_);
    proj_wmma_kernel<KP2, 3><<<divup(NA_, 128), 256, proj_smem<KP2,3>()>>>(
        x16a, Wt, qa, kv0, kv0 + 32, (__half*)0, (__half*)0, NA_);
}

static void run_agg_out(const LayerW& L, int use_skip,
                        const float* xa_skip, const float* xp_skip,
                        float* outa, float* outp, __half* outa16, __half* outp16,
                        float* qa, float* qp,
                        __half* kv0, __half* kv1, __half* kv2,
                        float* xa_agg, float* xp_agg,
                        const int* permA, const int* permP,
                        const int* rp_w, const int* cs_w,
                        const int* rp_b, const int* cs_b,
                        const int* rp_c, const int* cs_c) {
    const int BT = 256;
    int gaA = divup(NA_, 64), gpA = divup(NP_, 64);
    agg2_kernel<<<gpA, BT>>>(permP, rp_w, cs_w, kv0, rp_c, cs_c, kv2, qp, xp_agg, NP_);
    agg1_kernel<<<gaA, BT>>>(permA, rp_b, cs_b, qa, kv1, xa_agg, NA_);

    int ga4 = divup(divup(NA_, 4) * 32, BT);
    int gp4 = divup(divup(NP_, 4) * 32, BT);
    out_kernel<<<ga4, BT>>>(xa_agg, L.Wa,        L.ba,      L.skip, 0, xa_skip, outa, outa16, NA_, use_skip);
    out_kernel<<<gp4, BT>>>(xp_agg, L.Wa + 1024, L.ba + 32, L.skip, 1, xp_skip, outp, outp16, NP_, use_skip);
}

extern "C" void kernel_launch(void* const* d_in, const int* in_sizes, int n_in,
                              void* d_out, int out_size) {
    const float* x_a   = (const float*)d_in[0];
    const float* x_p   = (const float*)d_in[1];
    const int* e_wr    = (const int*)d_in[2];
    const int* e_wb    = (const int*)d_in[3];
    const int* e_ci    = (const int*)d_in[4];
    LayerW L1 = { (const float*)d_in[5],  (const float*)d_in[6],
                  (const float*)d_in[7],  (const float*)d_in[8],
                  (const float*)d_in[9],  (const float*)d_in[10],
                  (const float*)d_in[11], (const float*)d_in[12],
                  (const float*)d_in[13], (const float*)d_in[14],
                  (const float*)d_in[15], (const float*)d_in[16] };
    LayerW L2 = { (const float*)d_in[17], (const float*)d_in[18],
                  (const float*)d_in[19], (const float*)d_in[20],
                  (const float*)d_in[21], (const float*)d_in[22],
                  (const float*)d_in[23], (const float*)d_in[24],
                  (const float*)d_in[25], (const float*)d_in[26],
                  (const float*)d_in[27], (const float*)d_in[28] };

    float *qa,*qp,*xa_agg,*xp_agg,*h1a,*h1p;
    __half *kv0,*kv1,*kv2,*x16a,*x16p,*Wt;
    int *hist,*permA,*permP;
    cudaGetSymbolAddress((void**)&qa, g_qa);   cudaGetSymbolAddress((void**)&qp, g_qp);
    cudaGetSymbolAddress((void**)&kv0, g_kv0);
    cudaGetSymbolAddress((void**)&kv1, g_kv1);
    cudaGetSymbolAddress((void**)&kv2, g_kv2);
    cudaGetSymbolAddress((void**)&xa_agg, g_xa);
    cudaGetSymbolAddress((void**)&xp_agg, g_xp);
    cudaGetSymbolAddress((void**)&h1a, g_h1a); cudaGetSymbolAddress((void**)&h1p, g_h1p);
    cudaGetSymbolAddress((void**)&x16a, g_x16a); cudaGetSymbolAddress((void**)&x16p, g_x16p);
    cudaGetSymbolAddress((void**)&Wt, g_Wt);
    cudaGetSymbolAddress((void**)&hist, g_hist);
    cudaGetSymbolAddress((void**)&permA, g_permA);
    cudaGetSymbolAddress((void**)&permP, g_permP);

    Rel3 R;
    R.e0 = e_ci; R.E0 = EC_;  R.n0 = NP_;
    R.e1 = e_wr; R.E1 = EW_;  R.n1 = NP_;
    R.e2 = e_wb; R.E2 = EWB_; R.n2 = NA_;
    cudaGetSymbolAddress((void**)&R.deg0, g_deg_c); cudaGetSymbolAddress((void**)&R.rp0, g_rp_c);
    cudaGetSymbolAddress((void**)&R.cs0, g_cs_c);   cudaGetSymbolAddress((void**)&R.bs0, g_bs_c);
    cudaGetSymbolAddress((void**)&R.deg1, g_deg_w); cudaGetSymbolAddress((void**)&R.rp1, g_rp_w);
    cudaGetSymbolAddress((void**)&R.cs1, g_cs_w);   cudaGetSymbolAddress((void**)&R.bs1, g_bs_w);
    cudaGetSymbolAddress((void**)&R.deg2, g_deg_b); cudaGetSymbolAddress((void**)&R.rp2, g_rp_b);
    cudaGetSymbolAddress((void**)&R.cs2, g_cs_b);   cudaGetSymbolAddress((void**)&R.bs2, g_bs_b);

    cudaFuncSetAttribute(proj_wmma_kernel<KP2_L1,3>, cudaFuncAttributeMaxDynamicSharedMemorySize,
                         proj_smem<KP2_L1,3>());
    cudaFuncSetAttribute(proj_wmma_kernel<KP2_L1,5>, cudaFuncAttributeMaxDynamicSharedMemorySize,
                         proj_smem<KP2_L1,5>());
    cudaFuncSetAttribute(proj_wmma_kernel<KP2_L2,3>, cudaFuncAttributeMaxDynamicSharedMemorySize,
                         proj_smem<KP2_L2,3>());
    cudaFuncSetAttribute(proj_wmma_kernel<KP2_L2,5>, cudaFuncAttributeMaxDynamicSharedMemorySize,
                         proj_smem<KP2_L2,5>());

    const int BT = 256;
    // cvt, cvt, compose, proj_p (ncu slot 4), proj_a, CSR, perm, aggs, outs.
    cvt16_kernel<<<divup(NA_*(KP2_L1/4), BT), BT>>>(x_a, x16a, NA_, 128, KP2_L1);
    cvt16_kernel<<<divup(NP_*(KP2_L1/4), BT), BT>>>(x_p, x16p, NP_, 128, KP2_L1);
    run_proj<KP2_L1>(x16a, x16p, 128, L1, qa, qp, kv0, kv1, kv2, Wt);

    int totE = EC_ + EW_ + EWB_;
    int totN = NP_ + NP_ + NA_;
    int nbmax = divup(NP_, 1024);
    zero_all_kernel<<<divup(totN, BT), BT>>>(R);
    count_all_kernel<<<divup(totE, BT), BT>>>(R);
    scan_p1_all<<<dim3(nbmax, 3), 256>>>(R);
    scan_p2_all<<<3, 256>>>(R);
    scan_p3_all<<<dim3(nbmax, 3), 256>>>(R);
    scatter_all_kernel<<<divup(totE, BT), BT>>>(R);

    // degree-binned permutations (agg load balance; shared by both layers)
    zero_hist_kernel<<<1, 128>>>(hist);
    key_count_kernel<<<divup(NA_ + NP_, BT), BT>>>(R.rp2, R.rp1, R.rp0, hist);
    hist_scan_kernel<<<1, 128>>>(hist);
    perm_scatter_kernel<<<divup(NA_ + NP_, BT), BT>>>(R.rp2, R.rp1, R.rp0, hist, permA, permP);

    // Layer 1 agg + out (emits fp16 copy with ones column for layer 2 input)
    run_agg_out(L1, 0, x_a, x_p, h1a, h1p, x16a, x16p,
                qa, qp, kv0, kv1, kv2, xa_agg, xp_agg, permA, permP,
                R.rp1, R.cs1, R.rp2, R.cs2, R.rp0, R.cs0);

    // Layer 2: 32 -> 32, gated skip.
    run_proj<KP2_L2>(x16a, x16p, 32, L2, qa, qp, kv0, kv1, kv2, Wt);
    float* out = (float*)d_out;
    run_agg_out(L2, 1, h1a, h1p, out, out + (size_t)NA_ * 32, (__half*)0, (__half*)0,
                qa, qp, kv0, kv1, kv2, xa_agg, xp_agg, permA, permP,
                R.rp1, R.cs1, R.rp2, R.cs2, R.rp0, R.cs0);
}

// round 15
// speedup vs baseline: 1.2703x; 1.2703x over previous
#include <cuda_runtime.h>
#include <cuda_fp16.h>
#include <mma.h>
#include <math.h>
#include <stdint.h>

#define NA_  100000
#define NP_  200000
#define EW_  1000000
#define EWB_ 1000000
#define EC_  2000000
#define KP2_L1 144   // 128 + 16 (ones/bias column block)
#define KP2_L2 48    // 32 + 16

// ---------------- scratch (device globals; no allocation allowed) ----------
__device__ float g_qa[(NA_+128)*32], g_qp[(NP_+128)*32];
__device__ __align__(32) __half g_kv0[(NA_+128)*64];   // authors as src (writes)
__device__ __align__(32) __half g_kv1[(NP_+128)*64];   // papers as src (written_by)
__device__ __align__(32) __half g_kv2[(NP_+128)*64];   // papers as src (cites)
__device__ float g_xa[NA_*32], g_xp[NP_*32];
__device__ float g_h1a[NA_*32], g_h1p[NP_*32];
__device__ __align__(32) __half g_x16a[NA_*KP2_L1], g_x16p[NP_*KP2_L1];
// CSR per relation (dst-indexed)
__device__ int g_deg_w[NP_], g_rp_w[NP_+1];  __device__ int g_cs_w[EW_];
__device__ int g_deg_b[NA_], g_rp_b[NA_+1];  __device__ int g_cs_b[EWB_];
__device__ int g_deg_c[NP_], g_rp_c[NP_+1];  __device__ int g_cs_c[EC_];
__device__ int g_bs_w[256], g_bs_b[256], g_bs_c[256];
// composite weights: 8 tasks x [32][KP2<=144] fp16 (col-major B, bias at row F)
__device__ __align__(32) __half g_Wt[8*32*KP2_L1];

// ---------------- helpers ---------------------------------------------------
__device__ __forceinline__ unsigned long long pack2(float lo, float hi) {
    unsigned long long r;
    asm("mov.b64 %0, {%1,%2};" : "=l"(r) : "f"(lo), "f"(hi));
    return r;
}
__device__ __forceinline__ void ffma2(unsigned long long& acc,
                                      unsigned long long a, unsigned long long b) {
    asm("fma.rn.f32x2 %0, %1, %2, %0;" : "+l"(acc) : "l"(a), "l"(b));
}
__device__ __forceinline__ float2 unpack2(unsigned long long v) {
    float2 r;
    asm("mov.b64 {%0,%1}, %2;" : "=f"(r.x), "=f"(r.y) : "l"(v));
    return r;
}
static inline int divup(int a, int b) { return (a + b - 1) / b; }

// ---------------- fused CSR build ----------------------------------------------
struct Rel3 {
    const int *e0, *e1, *e2;
    int E0, E1, E2;
    int n0, n1, n2;
    int *deg0, *deg1, *deg2;
    int *rp0, *rp1, *rp2;
    int *cs0, *cs1, *cs2;
    int *bs0, *bs1, *bs2;
};

__global__ void zero_all_kernel(Rel3 R) {
    int i = blockIdx.x * blockDim.x + threadIdx.x;
    int t = R.n0 + R.n1 + R.n2;
    if (i >= t) return;
    if (i < R.n0) R.deg0[i] = 0;
    else if (i < R.n0 + R.n1) R.deg1[i - R.n0] = 0;
    else R.deg2[i - R.n0 - R.n1] = 0;
}
__global__ void count_all_kernel(Rel3 R) {
    int i = blockIdx.x * blockDim.x + threadIdx.x;
    if (i < R.E0) { atomicAdd(&R.deg0[__ldg(R.e0 + R.E0 + i)], 1); return; }
    i -= R.E0;
    if (i < R.E1) { atomicAdd(&R.deg1[__ldg(R.e1 + R.E1 + i)], 1); return; }
    i -= R.E1;
    if (i < R.E2) { atomicAdd(&R.deg2[__ldg(R.e2 + R.E2 + i)], 1); }
}
__device__ __forceinline__ void rel_sel(const Rel3& R, int r, const int*& deg, int& n, int*& bsum) {
    if (r == 0) { deg = R.deg0; n = R.n0; bsum = R.bs0; }
    else if (r == 1) { deg = R.deg1; n = R.n1; bsum = R.bs1; }
    else { deg = R.deg2; n = R.n2; bsum = R.bs2; }
}
__global__ void scan_p1_all(Rel3 R) {
    const int* deg; int n; int* bsum;
    rel_sel(R, blockIdx.y, deg, n, bsum);
    int base = blockIdx.x * 1024;
    if (base >= n) return;
    __shared__ int sm[256];
    int t = threadIdx.x;
    int s = 0;
#pragma unroll
    for (int j = 0; j < 4; j++) {
        int i = base + t * 4 + j;
        if (i < n) s += deg[i];
    }
    sm[t] = s; __syncthreads();
#pragma unroll
    for (int o = 128; o > 0; o >>= 1) {
        if (t < o) sm[t] += sm[t + o];
        __syncthreads();
    }
    if (t == 0) bsum[blockIdx.x] = sm[0];
}
__global__ void scan_p2_all(Rel3 R) {
    const int* degc; int n; int* bsum;
    rel_sel(R, blockIdx.x, degc, n, bsum);
    int* rp_last = (blockIdx.x == 0 ? R.rp0 : blockIdx.x == 1 ? R.rp1 : R.rp2) + n;
    int nb = (n + 1023) / 1024;
    __shared__ int sm[256];
    int t = threadIdx.x;
    int v = (t < nb) ? bsum[t] : 0;
    sm[t] = v; __syncthreads();
    for (int o = 1; o < 256; o <<= 1) {
        int x = (t >= o) ? sm[t - o] : 0;
        __syncthreads();
        sm[t] += x;
        __syncthreads();
    }
    if (t < nb) bsum[t] = sm[t] - v;
    if (t == 255) *rp_last = sm[255];
}
__global__ void scan_p3_all(Rel3 R) {
    const int* deg; int n; int* bsum;
    rel_sel(R, blockIdx.y, deg, n, bsum);
    int* rp  = (blockIdx.y == 0 ? R.rp0  : blockIdx.y == 1 ? R.rp1  : R.rp2);
    int* cur = (blockIdx.y == 0 ? R.deg0 : blockIdx.y == 1 ? R.deg1 : R.deg2);
    int base = blockIdx.x * 1024;
    if (base >= n) return;
    __shared__ int sm[256];
    int t = threadIdx.x;
    int v[4]; int s = 0;
#pragma unroll
    for (int j = 0; j < 4; j++) {
        int i = base + t * 4 + j;
        v[j] = (i < n) ? deg[i] : 0;
        s += v[j];
    }
    sm[t] = s; __syncthreads();
    for (int o = 1; o < 256; o <<= 1) {
        int x = (t >= o) ? sm[t - o] : 0;
        __syncthreads();
        sm[t] += x;
        __syncthreads();
    }
    int run = bsum[blockIdx.x] + sm[t] - s;
#pragma unroll
    for (int j = 0; j < 4; j++) {
        int i = base + t * 4 + j;
        if (i < n) { rp[i] = run; cur[i] = run; }
        run += v[j];
    }
}
__global__ void scatter_all_kernel(Rel3 R) {
    int i = blockIdx.x * blockDim.x + threadIdx.x;
    const int* e; int E; int* cur; int* cs;
    if (i < R.E0) { e = R.e0; E = R.E0; cur = R.deg0; cs = R.cs0; }
    else {
        i -= R.E0;
        if (i < R.E1) { e = R.e1; E = R.E1; cur = R.deg1; cs = R.cs1; }
        else {
            i -= R.E1;
            if (i >= R.E2) return;
            e = R.e2; E = R.E2; cur = R.deg2; cs = R.cs2;
        }
    }
    int slot = atomicAdd(&cur[__ldg(e + E + i)], 1);
    cs[slot] = __ldg(e + i);
}

// ---------------- weight composition (all 8 tasks, one launch) -----------------
struct CTask { const float* W; const float* b; const float* T; int prel_idx; };
struct CArgs { CTask t[8]; const float* prel; };

__global__ void compose_all_kernel(CArgs args, int F, int KP2, __half* __restrict__ Wt) {
    int task = blockIdx.y;
    int gw   = (blockIdx.x * blockDim.x + threadIdx.x) >> 5;
    int lane = threadIdx.x & 31;
    if (gw >= KP2) return;
    CTask tk = args.t[task];
    __half* dst = &Wt[((size_t)task * 32 + lane) * KP2 + gw];
    if (gw > F) { *dst = __float2half(0.f); return; }
    float scale = (tk.prel_idx >= 0) ? (__ldg(args.prel + tk.prel_idx) * 0.17677669529663687f) : 1.0f;
    float rv = (gw == F) ? tk.b[lane] : tk.W[(size_t)gw * 32 + lane];
    float acc;
    if (tk.T) {
        acc = 0.f;
#pragma unroll
        for (int j = 0; j < 32; j++) {
            float rj = __shfl_sync(0xffffffffu, rv, j);
            acc = fmaf(rj, __ldg(tk.T + j * 32 + lane), acc);
        }
    } else acc = rv;
    *dst = __float2half(acc * scale);
}

// ---------------- fp32 -> fp16 conversion with ones column ----------------------
__global__ void cvt16_kernel(const float* __restrict__ x, __half* __restrict__ y,
                             int n, int F, int KP2) {
    int i = blockIdx.x * blockDim.x + threadIdx.x;
    int cpr = KP2 >> 2;
    int total = n * cpr;
    if (i >= total) return;
    int node = i / cpr;
    int c4 = (i % cpr) << 2;
    float4 v = make_float4(0.f, 0.f, 0.f, 0.f);
    if (c4 < F)       v = __ldg((const float4*)(x + (size_t)node * F + c4));
    else if (c4 == F) v.x = 1.0f;
    __half2 h0 = __floats2half2_rn(v.x, v.y);
    __half2 h1 = __floats2half2_rn(v.z, v.w);
    __half2* dst = (__half2*)(y + (size_t)node * KP2 + c4);
    dst[0] = h0; dst[1] = h1;
}

// ---------------- wmma (HMMA) projection — direct-store, bias-folded ------------
template<int KP2, int NMAT>
__global__ void __launch_bounds__(256) proj_wmma_kernel(
        const __half* __restrict__ x16, const __half* __restrict__ Wt,
        float* __restrict__ qout,
        __half* __restrict__ o1, __half* __restrict__ o2,
        __half* __restrict__ o3, __half* __restrict__ o4, int n) {
    extern __shared__ __align__(32) __half smem_h[];
    const int LD = KP2 + 8;
    __half* sB = smem_h;
    __half* sA = sB + NMAT * 32 * LD;
    int tid = threadIdx.x, wid = tid >> 5;
    int base = blockIdx.x * 128;
    const int CH = KP2 / 8;
    for (int idx = tid; idx < NMAT * 32 * CH; idx += 256) {
        int r = idx / CH, c8 = (idx % CH) * 8;
        *(uint4*)(sB + r * LD + c8) = *(const uint4*)(Wt + (size_t)r * KP2 + c8);
    }
    for (int idx = tid; idx < 128 * CH; idx += 256) {
        int row = idx / CH, c8 = (idx % CH) * 8;
        uint4 v = make_uint4(0, 0, 0, 0);
        if (base + row < n) v = *(const uint4*)(x16 + (size_t)(base + row) * KP2 + c8);
        *(uint4*)(sA + row * LD + c8) = v;
    }
    __syncthreads();

    using namespace nvcuda;
    int m0 = wid * 16;
    int node0 = base + m0;
    wmma::fragment<wmma::accumulator, 16, 16, 16, float> q0f, q1f;
    wmma::fill_fragment(q0f, 0.f);
    wmma::fill_fragment(q1f, 0.f);
    wmma::fragment<wmma::accumulator, 16, 16, 16, __half> ah[NMAT-1][2];
#pragma unroll
    for (int m = 0; m < NMAT-1; m++) {
        wmma::fill_fragment(ah[m][0], __float2half(0.f));
        wmma::fill_fragment(ah[m][1], __float2half(0.f));
    }

#pragma unroll
    for (int k0 = 0; k0 < KP2; k0 += 16) {
        wmma::fragment<wmma::matrix_a, 16, 16, 16, __half, wmma::row_major> fa;
        wmma::load_matrix_sync(fa, sA + m0 * LD + k0, LD);
        {
            wmma::fragment<wmma::matrix_b, 16, 16, 16, __half, wmma::col_major> fb0, fb1;
            wmma::load_matrix_sync(fb0, sB + k0, LD);
            wmma::load_matrix_sync(fb1, sB + 16 * LD + k0, LD);
            wmma::mma_sync(q0f, fa, fb0, q0f);
            wmma::mma_sync(q1f, fa, fb1, q1f);
        }
#pragma unroll
        for (int m = 1; m < NMAT; m++) {
            wmma::fragment<wmma::matrix_b, 16, 16, 16, __half, wmma::col_major> fb0, fb1;
            const __half* Bm = sB + m * 32 * LD;
            wmma::load_matrix_sync(fb0, Bm + k0, LD);
            wmma::load_matrix_sync(fb1, Bm + 16 * LD + k0, LD);
            wmma::mma_sync(ah[m-1][0], fa, fb0, ah[m-1][0]);
            wmma::mma_sync(ah[m-1][1], fa, fb1, ah[m-1][1]);
        }
    }
    wmma::store_matrix_sync(qout + (size_t)node0 * 32,      q0f, 32, wmma::mem_row_major);
    wmma::store_matrix_sync(qout + (size_t)node0 * 32 + 16, q1f, 32, wmma::mem_row_major);
    __half* outs[4] = {o1, o2, o3, o4};
#pragma unroll
    for (int m = 1; m < NMAT; m++) {
        wmma::store_matrix_sync(outs[m-1] + (size_t)node0 * 64,      ah[m-1][0], 64, wmma::mem_row_major);
        wmma::store_matrix_sync(outs[m-1] + (size_t)node0 * 64 + 16, ah[m-1][1], 64, wmma::mem_row_major);
    }
}
template<int KP2, int NMAT>
static constexpr int proj_smem() {
    return (NMAT*32 + 128) * (KP2+8) * 2;
}

// ---------------- dst-centric edge aggregation (8 dst/warp, 4 lanes/dst) -------
// Masked-remainder: the tail (1-3 edges) is handled by ONE predicated unroll-4
// iteration (clamped indices, ex zero-masked) instead of serial single-edge steps.
__device__ __forceinline__ float edge_score(const uint4& kh, const float4& q0, const float4& q1) {
    float2 k0 = __half22float2(*(const __half2*)&kh.x);
    float2 k1 = __half22float2(*(const __half2*)&kh.y);
    float2 k2 = __half22float2(*(const __half2*)&kh.z);
    float2 k3 = __half22float2(*(const __half2*)&kh.w);
    return q0.x*k0.x + q0.y*k0.y + q0.z*k1.x + q0.w*k1.y
         + q1.x*k2.x + q1.y*k2.y + q1.z*k3.x + q1.w*k3.y;
}
__device__ __forceinline__ void edge_accum(unsigned long long acc[4], const uint4& vh, float ex) {
    unsigned long long ex2 = pack2(ex, ex);
    float2 v0 = __half22float2(*(const __half2*)&vh.x);
    float2 v1 = __half22float2(*(const __half2*)&vh.y);
    float2 v2 = __half22float2(*(const __half2*)&vh.z);
    float2 v3 = __half22float2(*(const __half2*)&vh.w);
    ffma2(acc[0], pack2(v0.x, v0.y), ex2);
    ffma2(acc[1], pack2(v1.x, v1.y), ex2);
    ffma2(acc[2], pack2(v2.x, v2.y), ex2);
    ffma2(acc[3], pack2(v3.x, v3.y), ex2);
}
__device__ __forceinline__ float accum_rel_h(int b0, int b1, const int* __restrict__ cs,
                                             const __half* __restrict__ kv,
                                             const float4& q0, const float4& q1,
                                             unsigned gmask, int ql,
                                             unsigned long long acc[4]) {
    float den = 0.f;
    int e = b0;
    for (; e + 4 <= b1; e += 4) {
        int s0 = __ldg(cs + e);
        int s1 = __ldg(cs + e + 1);
        int s2 = __ldg(cs + e + 2);
        int s3 = __ldg(cs + e + 3);
        const uint4* r0 = (const uint4*)(kv + (size_t)s0 * 64);
        const uint4* r1 = (const uint4*)(kv + (size_t)s1 * 64);
        const uint4* r2 = (const uint4*)(kv + (size_t)s2 * 64);
        const uint4* r3 = (const uint4*)(kv + (size_t)s3 * 64);
        uint4 k0 = __ldg(r0 + ql),     k1 = __ldg(r1 + ql);
        uint4 k2 = __ldg(r2 + ql),     k3 = __ldg(r3 + ql);
        uint4 v0 = __ldg(r0 + 4 + ql), v1 = __ldg(r1 + 4 + ql);
        uint4 v2 = __ldg(r2 + 4 + ql), v3 = __ldg(r3 + 4 + ql);
        float sc0 = edge_score(k0, q0, q1);
        float sc1 = edge_score(k1, q0, q1);
        float sc2 = edge_score(k2, q0, q1);
        float sc3 = edge_score(k3, q0, q1);
        sc0 += __shfl_xor_sync(gmask, sc0, 1);
        sc1 += __shfl_xor_sync(gmask, sc1, 1);
        sc2 += __shfl_xor_sync(gmask, sc2, 1);
        sc3 += __shfl_xor_sync(gmask, sc3, 1);
        sc0 += __shfl_xor_sync(gmask, sc0, 2);
        sc1 += __shfl_xor_sync(gmask, sc1, 2);
        sc2 += __shfl_xor_sync(gmask, sc2, 2);
        sc3 += __shfl_xor_sync(gmask, sc3, 2);
        float ex0 = __expf(fminf(sc0, 60.0f));
        float ex1 = __expf(fminf(sc1, 60.0f));
        float ex2 = __expf(fminf(sc2, 60.0f));
        float ex3 = __expf(fminf(sc3, 60.0f));
        edge_accum(acc, v0, ex0);
        edge_accum(acc, v1, ex1);
        edge_accum(acc, v2, ex2);
        edge_accum(acc, v3, ex3);
        den += (ex0 + ex1) + (ex2 + ex3);
    }
    if (e < b1) {
        int last = b1 - 1;
        int e1i = min(e + 1, last), e2i = min(e + 2, last), e3i = min(e + 3, last);
        int s0 = __ldg(cs + e);
        int s1 = __ldg(cs + e1i);
        int s2 = __ldg(cs + e2i);
        int s3 = __ldg(cs + e3i);
        const uint4* r0 = (const uint4*)(kv + (size_t)s0 * 64);
        const uint4* r1 = (const uint4*)(kv + (size_t)s1 * 64);
        const uint4* r2 = (const uint4*)(kv + (size_t)s2 * 64);
        const uint4* r3 = (const uint4*)(kv + (size_t)s3 * 64);
        uint4 k0 = __ldg(r0 + ql),     k1 = __ldg(r1 + ql);
        uint4 k2 = __ldg(r2 + ql),     k3 = __ldg(r3 + ql);
        uint4 v0 = __ldg(r0 + 4 + ql), v1 = __ldg(r1 + 4 + ql);
        uint4 v2 = __ldg(r2 + 4 + ql), v3 = __ldg(r3 + 4 + ql);
        float sc0 = edge_score(k0, q0, q1);
        float sc1 = edge_score(k1, q0, q1);
        float sc2 = edge_score(k2, q0, q1);
        float sc3 = edge_score(k3, q0, q1);
        sc0 += __shfl_xor_sync(gmask, sc0, 1);
        sc1 += __shfl_xor_sync(gmask, sc1, 1);
        sc2 += __shfl_xor_sync(gmask, sc2, 1);
        sc3 += __shfl_xor_sync(gmask, sc3, 1);
        sc0 += __shfl_xor_sync(gmask, sc0, 2);
        sc1 += __shfl_xor_sync(gmask, sc1, 2);
        sc2 += __shfl_xor_sync(gmask, sc2, 2);
        sc3 += __shfl_xor_sync(gmask, sc3, 2);
        float ex0 = __expf(fminf(sc0, 60.0f));
        float ex1 = (e + 1 < b1) ? __expf(fminf(sc1, 60.0f)) : 0.f;
        float ex2 = (e + 2 < b1) ? __expf(fminf(sc2, 60.0f)) : 0.f;
        float ex3 = (e + 3 < b1) ? __expf(fminf(sc3, 60.0f)) : 0.f;
        edge_accum(acc, v0, ex0);
        edge_accum(acc, v1, ex1);
        edge_accum(acc, v2, ex2);
        edge_accum(acc, v3, ex3);
        den += (ex0 + ex1) + (ex2 + ex3);
    }
    return den;
}
__global__ void agg1_kernel(const int* __restrict__ rp, const int* __restrict__ cs,
                            const float* __restrict__ q, const __half* __restrict__ kv,
                            float* __restrict__ xout, int n) {
    int gw   = (blockIdx.x * blockDim.x + threadIdx.x) >> 5;
    int lane = threadIdx.x & 31;
    int sub  = lane >> 2;
    int ql   = lane & 3;
    unsigned gmask = 0xFu << (sub * 4);
    int d = gw * 8 + sub;
    bool valid = (d < n);
    int dd = valid ? d : (n - 1);
    int b0 = __ldg(rp + dd);
    int b1 = valid ? __ldg(rp + dd + 1) : b0;
    float4 q0 = __ldg((const float4*)(q + (size_t)dd * 32) + ql * 2);
    float4 q1 = __ldg((const float4*)(q + (size_t)dd * 32) + ql * 2 + 1);
    unsigned long long acc[4];
    acc[0] = acc[1] = acc[2] = acc[3] = pack2(0.f, 0.f);
    float den = accum_rel_h(b0, b1, cs, kv, q0, q1, gmask, ql, acc);
    if (valid) {
        float inv = (den > 0.f) ? (1.0f / den) : 0.0f;
        float2 a0 = unpack2(acc[0]), a1 = unpack2(acc[1]);
        float2 a2 = unpack2(acc[2]), a3 = unpack2(acc[3]);
        *((float4*)(xout + (size_t)d * 32) + ql * 2)     = make_float4(a0.x*inv, a0.y*inv, a1.x*inv, a1.y*inv);
        *((float4*)(xout + (size_t)d * 32) + ql * 2 + 1) = make_float4(a2.x*inv, a2.y*inv, a3.x*inv, a3.y*inv);
    }
}
__global__ void agg2_kernel(const int* __restrict__ rp1, const int* __restrict__ cs1,
                            const __half* __restrict__ kvA,
                            const int* __restrict__ rp2, const int* __restrict__ cs2,
                            const __half* __restrict__ kvB,
                            const float* __restrict__ q,
                            float* __restrict__ xout, int n) {
    int gw   = (blockIdx.x * blockDim.x + threadIdx.x) >> 5;
    int lane = threadIdx.x & 31;
    int sub  = lane >> 2;
    int ql   = lane & 3;
    unsigned gmask = 0xFu << (sub * 4);
    int d = gw * 8 + sub;
    bool valid = (d < n);
    int dd = valid ? d : (n - 1);
    float4 q0 = __ldg((const float4*)(q + (size_t)dd * 32) + ql * 2);
    float4 q1 = __ldg((const float4*)(q + (size_t)dd * 32) + ql * 2 + 1);
    int a0 = __ldg(rp1 + dd);
    int a1 = valid ? __ldg(rp1 + dd + 1) : a0;
    int c0 = __ldg(rp2 + dd);
    int c1 = valid ? __ldg(rp2 + dd + 1) : c0;
    unsigned long long accA[4], accB[4];
    accA[0]=accA[1]=accA[2]=accA[3]=pack2(0.f,0.f);
    accB[0]=accB[1]=accB[2]=accB[3]=pack2(0.f,0.f);
    float denA = accum_rel_h(a0, a1, cs1, kvA, q0, q1, gmask, ql, accA);
    float denB = accum_rel_h(c0, c1, cs2, kvB, q0, q1, gmask, ql, accB);
    if (valid) {
        float invA = (denA > 0.f) ? (1.0f / denA) : 0.0f;
        float invB = (denB > 0.f) ? (1.0f / denB) : 0.0f;
        float2 rA[4], rB[4];
#pragma unroll
        for (int i = 0; i < 4; i++) { rA[i] = unpack2(accA[i]); rB[i] = unpack2(accB[i]); }
        *((float4*)(xout + (size_t)d * 32) + ql * 2) =
            make_float4(rA[0].x*invA + rB[0].x*invB, rA[0].y*invA + rB[0].y*invB,
                        rA[1].x*invA + rB[1].x*invB, rA[1].y*invA + rB[1].y*invB);
        *((float4*)(xout + (size_t)d * 32) + ql * 2 + 1) =
            make_float4(rA[2].x*invA + rB[2].x*invB, rA[2].y*invA + rB[2].y*invB,
                        rA[3].x*invA + rB[3].x*invB, rA[3].y*invA + rB[3].y*invB);
    }
}

// ---------------- output transform ---------------------------------------------
__global__ void out_kernel(const float* __restrict__ x1,
                           const float* __restrict__ Wa, const float* __restrict__ ba,
                           const float* __restrict__ skipv, int t_idx,
                           const float* __restrict__ xin,
                           float* __restrict__ out, __half* __restrict__ out16,
                           int n, int use_skip) {
    __shared__ float sW[1024];
    for (int i = threadIdx.x; i < 1024; i += blockDim.x) sW[i] = Wa[i];
    __syncthreads();
    int lane = threadIdx.x & 31;
    int gw = blockIdx.x * (blockDim.x >> 5) + (threadIdx.x >> 5);
    int n0 = gw * 4;
    if (n0 >= n) return;
    int m = n - n0; if (m > 4) m = 4;

    float4 xr[4];
#pragma unroll
    for (int j = 0; j < 4; j++) {
        if (j < m && lane < 8) {
            float4 a = __ldg((const float4*)(x1 + (size_t)(n0 + j) * 32) + lane);
            a.x = 0.5f * a.x * (1.0f + erff(a.x * 0.7071067811865475f));
            a.y = 0.5f * a.y * (1.0f + erff(a.y * 0.7071067811865475f));
            a.z = 0.5f * a.z * (1.0f + erff(a.z * 0.7071067811865475f));
            a.w = 0.5f * a.w * (1.0f + erff(a.w * 0.7071067811865475f));
            xr[j] = a;
        } else {
            xr[j] = make_float4(0.f, 0.f, 0.f, 0.f);
        }
    }
    unsigned long long A01 = pack2(ba[lane], ba[lane]), A23 = A01;
    for (int i0 = 0; i0 < 32; i0 += 4) {
        int sl = i0 >> 2;
        float xs[4][4];
#pragma unroll
        for (int j = 0; j < 4; j++) {
            xs[j][0] = __shfl_sync(0xffffffffu, xr[j].x, sl);
            xs[j][1] = __shfl_sync(0xffffffffu, xr[j].y, sl);
            xs[j][2] = __shfl_sync(0xffffffffu, xr[j].z, sl);
            xs[j][3] = __shfl_sync(0xffffffffu, xr[j].w, sl);
        }
#pragma unroll
        for (int c = 0; c < 4; c++) {
            float w = sW[(i0 + c) * 32 + lane];
            unsigned long long w2 = pack2(w, w);
            ffma2(A01, pack2(xs[0][c], xs[1][c]), w2);
            ffma2(A23, pack2(xs[2][c], xs[3][c]), w2);
        }
    }
    float2 a01 = unpack2(A01), a23 = unpack2(A23);
    float o[4] = {a01.x, a01.y, a23.x, a23.y};
    if (use_skip) {
        float a = 1.0f / (1.0f + expf(-__ldg(skipv + t_idx)));
#pragma unroll
        for (int j = 0; j < 4; j++) {
            if (j < m)
                o[j] = a * o[j] + (1.0f - a) * __ldg(xin + (size_t)(n0 + j) * 32 + lane);
        }
    }
#pragma unroll
    for (int j = 0; j < 4; j++) {
        if (j < m) {
            out[(size_t)(n0 + j) * 32 + lane] = o[j];
            if (out16) {
                out16[(size_t)(n0 + j) * KP2_L2 + lane] = __float2half(o[j]);
                if (lane < 16)
                    out16[(size_t)(n0 + j) * KP2_L2 + 32 + lane] =
                        __float2half(lane == 0 ? 1.0f : 0.0f);
            }
        }
    }
}

// ---------------- host orchestration ----------------------------------------
struct LayerW {
    const float *Wk, *bk, *Wq, *bq, *Wv, *bv, *Wa, *ba, *skip, *arel, *mrel, *prel;
};

template<int KP2>
static void run_proj(const __half* x16a, const __half* x16p, int F,
                     const LayerW& L,
                     float* qa, float* qp,
                     __half* kv0, __half* kv1, __half* kv2,
                     __half* Wt) {
    const int BT = 256;
    int wsz = F * 32;
    CArgs ca;
    ca.prel = L.prel;
    ca.t[0] = { L.Wq,       L.bq,      (const float*)0, -1 };
    ca.t[1] = { L.Wk,       L.bk,      L.arel + 0,      0  };
    ca.t[2] = { L.Wv,       L.bv,      L.mrel + 0,      -1 };
    ca.t[3] = { L.Wq + wsz, L.bq + 32, (const float*)0, -1 };
    ca.t[4] = { L.Wk + wsz, L.bk + 32, L.arel + 1024,   1  };
    ca.t[5] = { L.Wv + wsz, L.bv + 32, L.mrel + 1024,   -1 };
    ca.t[6] = { L.Wk + wsz, L.bk + 32, L.arel + 2048,   2  };
    ca.t[7] = { L.Wv + wsz, L.bv + 32, L.mrel + 2048,   -1 };
    dim3 cg(divup(KP2 * 32, BT), 8);
    compose_all_kernel<<<cg, BT>>>(ca, F, KP2, Wt);

    proj_wmma_kernel<KP2, 5><<<divup(NP_, 128), 256, proj_smem<KP2,5>()>>>(
        x16p, Wt + (size_t)3 * 32 * KP2, qp,
        kv1, kv1 + 32, kv2, kv2 + 32, NP_);
    proj_wmma_kernel<KP2, 3><<<divup(NA_, 128), 256, proj_smem<KP2,3>()>>>(
        x16a, Wt, qa, kv0, kv0 + 32, (__half*)0, (__half*)0, NA_);
}

static void run_agg_out(const LayerW& L, int use_skip,
                        const float* xa_skip, const float* xp_skip,
                        float* outa, float* outp, __half* outa16, __half* outp16,
                        float* qa, float* qp,
                        __half* kv0, __half* kv1, __half* kv2,
                        float* xa_agg, float* xp_agg,
                        const int* rp_w, const int* cs_w,
                        const int* rp_b, const int* cs_b,
                        const int* rp_c, const int* cs_c) {
    const int BT = 256;
    int gaA = divup(NA_, 64), gpA = divup(NP_, 64);
    agg2_kernel<<<gpA, BT>>>(rp_w, cs_w, kv0, rp_c, cs_c, kv2, qp, xp_agg, NP_);
    agg1_kernel<<<gaA, BT>>>(rp_b, cs_b, qa, kv1, xa_agg, NA_);

    int ga4 = divup(divup(NA_, 4) * 32, BT);
    int gp4 = divup(divup(NP_, 4) * 32, BT);
    out_kernel<<<ga4, BT>>>(xa_agg, L.Wa,        L.ba,      L.skip, 0, xa_skip, outa, outa16, NA_, use_skip);
    out_kernel<<<gp4, BT>>>(xp_agg, L.Wa + 1024, L.ba + 32, L.skip, 1, xp_skip, outp, outp16, NP_, use_skip);
}

extern "C" void kernel_launch(void* const* d_in, const int* in_sizes, int n_in,
                              void* d_out, int out_size) {
    const float* x_a   = (const float*)d_in[0];
    const float* x_p   = (const float*)d_in[1];
    const int* e_wr    = (const int*)d_in[2];
    const int* e_wb    = (const int*)d_in[3];
    const int* e_ci    = (const int*)d_in[4];
    LayerW L1 = { (const float*)d_in[5],  (const float*)d_in[6],
                  (const float*)d_in[7],  (const float*)d_in[8],
                  (const float*)d_in[9],  (const float*)d_in[10],
                  (const float*)d_in[11], (const float*)d_in[12],
                  (const float*)d_in[13], (const float*)d_in[14],
                  (const float*)d_in[15], (const float*)d_in[16] };
    LayerW L2 = { (const float*)d_in[17], (const float*)d_in[18],
                  (const float*)d_in[19], (const float*)d_in[20],
                  (const float*)d_in[21], (const float*)d_in[22],
                  (const float*)d_in[23], (const float*)d_in[24],
                  (const float*)d_in[25], (const float*)d_in[26],
                  (const float*)d_in[27], (const float*)d_in[28] };

    float *qa,*qp,*xa_agg,*xp_agg,*h1a,*h1p;
    __half *kv0,*kv1,*kv2,*x16a,*x16p,*Wt;
    cudaGetSymbolAddress((void**)&qa, g_qa);   cudaGetSymbolAddress((void**)&qp, g_qp);
    cudaGetSymbolAddress((void**)&kv0, g_kv0);
    cudaGetSymbolAddress((void**)&kv1, g_kv1);
    cudaGetSymbolAddress((void**)&kv2, g_kv2);
    cudaGetSymbolAddress((void**)&xa_agg, g_xa);
    cudaGetSymbolAddress((void**)&xp_agg, g_xp);
    cudaGetSymbolAddress((void**)&h1a, g_h1a); cudaGetSymbolAddress((void**)&h1p, g_h1p);
    cudaGetSymbolAddress((void**)&x16a, g_x16a); cudaGetSymbolAddress((void**)&x16p, g_x16p);
    cudaGetSymbolAddress((void**)&Wt, g_Wt);

    Rel3 R;
    R.e0 = e_ci; R.E0 = EC_;  R.n0 = NP_;
    R.e1 = e_wr; R.E1 = EW_;  R.n1 = NP_;
    R.e2 = e_wb; R.E2 = EWB_; R.n2 = NA_;
    cudaGetSymbolAddress((void**)&R.deg0, g_deg_c); cudaGetSymbolAddress((void**)&R.rp0, g_rp_c);
    cudaGetSymbolAddress((void**)&R.cs0, g_cs_c);   cudaGetSymbolAddress((void**)&R.bs0, g_bs_c);
    cudaGetSymbolAddress((void**)&R.deg1, g_deg_w); cudaGetSymbolAddress((void**)&R.rp1, g_rp_w);
    cudaGetSymbolAddress((void**)&R.cs1, g_cs_w);   cudaGetSymbolAddress((void**)&R.bs1, g_bs_w);
    cudaGetSymbolAddress((void**)&R.deg2, g_deg_b); cudaGetSymbolAddress((void**)&R.rp2, g_rp_b);
    cudaGetSymbolAddress((void**)&R.cs2, g_cs_b);   cudaGetSymbolAddress((void**)&R.bs2, g_bs_b);

    cudaFuncSetAttribute(proj_wmma_kernel<KP2_L1,3>, cudaFuncAttributeMaxDynamicSharedMemorySize,
                         proj_smem<KP2_L1,3>());
    cudaFuncSetAttribute(proj_wmma_kernel<KP2_L1,5>, cudaFuncAttributeMaxDynamicSharedMemorySize,
                         proj_smem<KP2_L1,5>());
    cudaFuncSetAttribute(proj_wmma_kernel<KP2_L2,3>, cudaFuncAttributeMaxDynamicSharedMemorySize,
                         proj_smem<KP2_L2,3>());
    cudaFuncSetAttribute(proj_wmma_kernel<KP2_L2,5>, cudaFuncAttributeMaxDynamicSharedMemorySize,
                         proj_smem<KP2_L2,5>());

    const int BT = 256;
    // cvt, cvt, compose, proj_p (ncu slot 4), proj_a, CSR, aggs, outs.
    cvt16_kernel<<<divup(NA_*(KP2_L1/4), BT), BT>>>(x_a, x16a, NA_, 128, KP2_L1);
    cvt16_kernel<<<divup(NP_*(KP2_L1/4), BT), BT>>>(x_p, x16p, NP_, 128, KP2_L1);
    run_proj<KP2_L1>(x16a, x16p, 128, L1, qa, qp, kv0, kv1, kv2, Wt);

    int totE = EC_ + EW_ + EWB_;
    int totN = NP_ + NP_ + NA_;
    int nbmax = divup(NP_, 1024);
    zero_all_kernel<<<divup(totN, BT), BT>>>(R);
    count_all_kernel<<<divup(totE, BT), BT>>>(R);
    scan_p1_all<<<dim3(nbmax, 3), 256>>>(R);
    scan_p2_all<<<3, 256>>>(R);
    scan_p3_all<<<dim3(nbmax, 3), 256>>>(R);
    scatter_all_kernel<<<divup(totE, BT), BT>>>(R);

    // Layer 1 agg + out (emits fp16 copy with ones column for layer 2 input)
    run_agg_out(L1, 0, x_a, x_p, h1a, h1p, x16a, x16p,
                qa, qp, kv0, kv1, kv2, xa_agg, xp_agg,
                R.rp1, R.cs1, R.rp2, R.cs2, R.rp0, R.cs0);

    // Layer 2: 32 -> 32, gated skip.
    run_proj<KP2_L2>(x16a, x16p, 32, L2, qa, qp, kv0, kv1, kv2, Wt);
    float* out = (float*)d_out;
    run_agg_out(L2, 1, h1a, h1p, out, out + (size_t)NA_ * 32, (__half*)0, (__half*)0,
                qa, qp, kv0, kv1, kv2, xa_agg, xp_agg,
                R.rp1, R.cs1, R.rp2, R.cs2, R.rp0, R.cs0);
}

// round 16
// speedup vs baseline: 1.3420x; 1.0564x over previous
#include <cuda_runtime.h>
#include <cuda_fp16.h>
#include <mma.h>
#include <math.h>
#include <stdint.h>

#define NA_  100000
#define NP_  200000
#define EW_  1000000
#define EWB_ 1000000
#define EC_  2000000
#define KP2_L1 144   // 128 + 16 (ones/bias column block)
#define KP2_L2 48    // 32 + 16

// ---------------- scratch (device globals; no allocation allowed) ----------
__device__ float g_qa[(NA_+128)*32], g_qp[(NP_+128)*32];
__device__ __align__(32) __half g_kv0[(NA_+128)*64];   // authors as src (writes)
__device__ __align__(32) __half g_kv1[(NP_+128)*64];   // papers as src (written_by)
__device__ __align__(32) __half g_kv2[(NP_+128)*64];   // papers as src (cites)
__device__ float g_xa[NA_*32], g_xp[NP_*32];
__device__ float g_h1a[NA_*32], g_h1p[NP_*32];
__device__ __align__(32) __half g_x16a[NA_*KP2_L2], g_x16p[NP_*KP2_L2];
// CSR per relation (dst-indexed)
__device__ int g_deg_w[NP_], g_rp_w[NP_+1];  __device__ int g_cs_w[EW_];
__device__ int g_deg_b[NA_], g_rp_b[NA_+1];  __device__ int g_cs_b[EWB_];
__device__ int g_deg_c[NP_], g_rp_c[NP_+1];  __device__ int g_cs_c[EC_];
__device__ int g_bs_w[256], g_bs_b[256], g_bs_c[256];
// composite weights: 8 tasks x [32][KP2<=144] fp16 (col-major B, bias at row F)
__device__ __align__(32) __half g_Wt[8*32*KP2_L1];

// ---------------- helpers ---------------------------------------------------
__device__ __forceinline__ unsigned long long pack2(float lo, float hi) {
    unsigned long long r;
    asm("mov.b64 %0, {%1,%2};" : "=l"(r) : "f"(lo), "f"(hi));
    return r;
}
__device__ __forceinline__ void ffma2(unsigned long long& acc,
                                      unsigned long long a, unsigned long long b) {
    asm("fma.rn.f32x2 %0, %1, %2, %0;" : "+l"(acc) : "l"(a), "l"(b));
}
__device__ __forceinline__ float2 unpack2(unsigned long long v) {
    float2 r;
    asm("mov.b64 {%0,%1}, %2;" : "=f"(r.x), "=f"(r.y) : "l"(v));
    return r;
}
static inline int divup(int a, int b) { return (a + b - 1) / b; }

// ---------------- fused CSR build ----------------------------------------------
struct Rel3 {
    const int *e0, *e1, *e2;
    int E0, E1, E2;
    int n0, n1, n2;
    int *deg0, *deg1, *deg2;
    int *rp0, *rp1, *rp2;
    int *cs0, *cs1, *cs2;
    int *bs0, *bs1, *bs2;
};

__global__ void zero_all_kernel(Rel3 R) {
    int i = blockIdx.x * blockDim.x + threadIdx.x;
    int t = R.n0 + R.n1 + R.n2;
    if (i >= t) return;
    if (i < R.n0) R.deg0[i] = 0;
    else if (i < R.n0 + R.n1) R.deg1[i - R.n0] = 0;
    else R.deg2[i - R.n0 - R.n1] = 0;
}
__global__ void count_all_kernel(Rel3 R) {
    int i = blockIdx.x * blockDim.x + threadIdx.x;
    if (i < R.E0) { atomicAdd(&R.deg0[__ldg(R.e0 + R.E0 + i)], 1); return; }
    i -= R.E0;
    if (i < R.E1) { atomicAdd(&R.deg1[__ldg(R.e1 + R.E1 + i)], 1); return; }
    i -= R.E1;
    if (i < R.E2) { atomicAdd(&R.deg2[__ldg(R.e2 + R.E2 + i)], 1); }
}
__device__ __forceinline__ void rel_sel(const Rel3& R, int r, const int*& deg, int& n, int*& bsum) {
    if (r == 0) { deg = R.deg0; n = R.n0; bsum = R.bs0; }
    else if (r == 1) { deg = R.deg1; n = R.n1; bsum = R.bs1; }
    else { deg = R.deg2; n = R.n2; bsum = R.bs2; }
}
__global__ void scan_p1_all(Rel3 R) {
    const int* deg; int n; int* bsum;
    rel_sel(R, blockIdx.y, deg, n, bsum);
    int base = blockIdx.x * 1024;
    if (base >= n) return;
    __shared__ int sm[256];
    int t = threadIdx.x;
    int s = 0;
#pragma unroll
    for (int j = 0; j < 4; j++) {
        int i = base + t * 4 + j;
        if (i < n) s += deg[i];
    }
    sm[t] = s; __syncthreads();
#pragma unroll
    for (int o = 128; o > 0; o >>= 1) {
        if (t < o) sm[t] += sm[t + o];
        __syncthreads();
    }
    if (t == 0) bsum[blockIdx.x] = sm[0];
}
__global__ void scan_p2_all(Rel3 R) {
    const int* degc; int n; int* bsum;
    rel_sel(R, blockIdx.x, degc, n, bsum);
    int* rp_last = (blockIdx.x == 0 ? R.rp0 : blockIdx.x == 1 ? R.rp1 : R.rp2) + n;
    int nb = (n + 1023) / 1024;
    __shared__ int sm[256];
    int t = threadIdx.x;
    int v = (t < nb) ? bsum[t] : 0;
    sm[t] = v; __syncthreads();
    for (int o = 1; o < 256; o <<= 1) {
        int x = (t >= o) ? sm[t - o] : 0;
        __syncthreads();
        sm[t] += x;
        __syncthreads();
    }
    if (t < nb) bsum[t] = sm[t] - v;
    if (t == 255) *rp_last = sm[255];
}
__global__ void scan_p3_all(Rel3 R) {
    const int* deg; int n; int* bsum;
    rel_sel(R, blockIdx.y, deg, n, bsum);
    int* rp  = (blockIdx.y == 0 ? R.rp0  : blockIdx.y == 1 ? R.rp1  : R.rp2);
    int* cur = (blockIdx.y == 0 ? R.deg0 : blockIdx.y == 1 ? R.deg1 : R.deg2);
    int base = blockIdx.x * 1024;
    if (base >= n) return;
    __shared__ int sm[256];
    int t = threadIdx.x;
    int v[4]; int s = 0;
#pragma unroll
    for (int j = 0; j < 4; j++) {
        int i = base + t * 4 + j;
        v[j] = (i < n) ? deg[i] : 0;
        s += v[j];
    }
    sm[t] = s; __syncthreads();
    for (int o = 1; o < 256; o <<= 1) {
        int x = (t >= o) ? sm[t - o] : 0;
        __syncthreads();
        sm[t] += x;
        __syncthreads();
    }
    int run = bsum[blockIdx.x] + sm[t] - s;
#pragma unroll
    for (int j = 0; j < 4; j++) {
        int i = base + t * 4 + j;
        if (i < n) { rp[i] = run; cur[i] = run; }
        run += v[j];
    }
}
__global__ void scatter_all_kernel(Rel3 R) {
    int i = blockIdx.x * blockDim.x + threadIdx.x;
    const int* e; int E; int* cur; int* cs;
    if (i < R.E0) { e = R.e0; E = R.E0; cur = R.deg0; cs = R.cs0; }
    else {
        i -= R.E0;
        if (i < R.E1) { e = R.e1; E = R.E1; cur = R.deg1; cs = R.cs1; }
        else {
            i -= R.E1;
            if (i >= R.E2) return;
            e = R.e2; E = R.E2; cur = R.deg2; cs = R.cs2;
        }
    }
    int slot = atomicAdd(&cur[__ldg(e + E + i)], 1);
    cs[slot] = __ldg(e + i);
}

// ---------------- weight composition (all 8 tasks, one launch) -----------------
struct CTask { const float* W; const float* b; const float* T; int prel_idx; };
struct CArgs { CTask t[8]; const float* prel; };

__global__ void compose_all_kernel(CArgs args, int F, int KP2, __half* __restrict__ Wt) {
    int task = blockIdx.y;
    int gw   = (blockIdx.x * blockDim.x + threadIdx.x) >> 5;
    int lane = threadIdx.x & 31;
    if (gw >= KP2) return;
    CTask tk = args.t[task];
    __half* dst = &Wt[((size_t)task * 32 + lane) * KP2 + gw];
    if (gw > F) { *dst = __float2half(0.f); return; }
    float scale = (tk.prel_idx >= 0) ? (__ldg(args.prel + tk.prel_idx) * 0.17677669529663687f) : 1.0f;
    float rv = (gw == F) ? tk.b[lane] : tk.W[(size_t)gw * 32 + lane];
    float acc;
    if (tk.T) {
        acc = 0.f;
#pragma unroll
        for (int j = 0; j < 32; j++) {
            float rj = __shfl_sync(0xffffffffu, rv, j);
            acc = fmaf(rj, __ldg(tk.T + j * 32 + lane), acc);
        }
    } else acc = rv;
    *dst = __float2half(acc * scale);
}

// ---------------- wmma (HMMA) projection — direct-store, bias-folded ------------
// F32IN: stage directly from fp32 x (stride F = KP2-16), converting to fp16 and
// synthesizing the ones/bias column. Otherwise input is fp16 with stride KP2.
template<int KP2, int NMAT, bool F32IN>
__global__ void __launch_bounds__(256) proj_wmma_kernel(
        const void* __restrict__ xin, const __half* __restrict__ Wt,
        float* __restrict__ qout,
        __half* __restrict__ o1, __half* __restrict__ o2,
        __half* __restrict__ o3, __half* __restrict__ o4, int n) {
    extern __shared__ __align__(32) __half smem_h[];
    const int LD = KP2 + 8;
    const int F = KP2 - 16;
    __half* sB = smem_h;
    __half* sA = sB + NMAT * 32 * LD;
    int tid = threadIdx.x, wid = tid >> 5;
    int base = blockIdx.x * 128;
    const int CH = KP2 / 8;
    for (int idx = tid; idx < NMAT * 32 * CH; idx += 256) {
        int r = idx / CH, c8 = (idx % CH) * 8;
        *(uint4*)(sB + r * LD + c8) = *(const uint4*)(Wt + (size_t)r * KP2 + c8);
    }
    for (int idx = tid; idx < 128 * CH; idx += 256) {
        int row = idx / CH, c8 = (idx % CH) * 8;
        bool rv = (base + row < n);
        if (F32IN) {
            __half2 h[4];
            if (rv && c8 < F) {
                const float4* xr = (const float4*)((const float*)xin + (size_t)(base + row) * F + c8);
                float4 a = __ldg(xr), b = __ldg(xr + 1);
                h[0] = __floats2half2_rn(a.x, a.y);
                h[1] = __floats2half2_rn(a.z, a.w);
                h[2] = __floats2half2_rn(b.x, b.y);
                h[3] = __floats2half2_rn(b.z, b.w);
            } else {
                float one = (rv && c8 == F) ? 1.0f : 0.0f;
                h[0] = __floats2half2_rn(one, 0.f);
                h[1] = h[2] = h[3] = __floats2half2_rn(0.f, 0.f);
            }
            *(uint4*)(sA + row * LD + c8) = *(uint4*)h;
        } else {
            uint4 v = make_uint4(0, 0, 0, 0);
            if (rv) v = *(const uint4*)((const __half*)xin + (size_t)(base + row) * KP2 + c8);
            *(uint4*)(sA + row * LD + c8) = v;
        }
    }
    __syncthreads();

    using namespace nvcuda;
    int m0 = wid * 16;
    int node0 = base + m0;
    wmma::fragment<wmma::accumulator, 16, 16, 16, float> q0f, q1f;
    wmma::fill_fragment(q0f, 0.f);
    wmma::fill_fragment(q1f, 0.f);
    wmma::fragment<wmma::accumulator, 16, 16, 16, __half> ah[NMAT-1][2];
#pragma unroll
    for (int m = 0; m < NMAT-1; m++) {
        wmma::fill_fragment(ah[m][0], __float2half(0.f));
        wmma::fill_fragment(ah[m][1], __float2half(0.f));
    }

#pragma unroll
    for (int k0 = 0; k0 < KP2; k0 += 16) {
        wmma::fragment<wmma::matrix_a, 16, 16, 16, __half, wmma::row_major> fa;
        wmma::load_matrix_sync(fa, sA + m0 * LD + k0, LD);
        {
            wmma::fragment<wmma::matrix_b, 16, 16, 16, __half, wmma::col_major> fb0, fb1;
            wmma::load_matrix_sync(fb0, sB + k0, LD);
            wmma::load_matrix_sync(fb1, sB + 16 * LD + k0, LD);
            wmma::mma_sync(q0f, fa, fb0, q0f);
            wmma::mma_sync(q1f, fa, fb1, q1f);
        }
#pragma unroll
        for (int m = 1; m < NMAT; m++) {
            wmma::fragment<wmma::matrix_b, 16, 16, 16, __half, wmma::col_major> fb0, fb1;
            const __half* Bm = sB + m * 32 * LD;
            wmma::load_matrix_sync(fb0, Bm + k0, LD);
            wmma::load_matrix_sync(fb1, Bm + 16 * LD + k0, LD);
            wmma::mma_sync(ah[m-1][0], fa, fb0, ah[m-1][0]);
            wmma::mma_sync(ah[m-1][1], fa, fb1, ah[m-1][1]);
        }
    }
    wmma::store_matrix_sync(qout + (size_t)node0 * 32,      q0f, 32, wmma::mem_row_major);
    wmma::store_matrix_sync(qout + (size_t)node0 * 32 + 16, q1f, 32, wmma::mem_row_major);
    __half* outs[4] = {o1, o2, o3, o4};
#pragma unroll
    for (int m = 1; m < NMAT; m++) {
        wmma::store_matrix_sync(outs[m-1] + (size_t)node0 * 64,      ah[m-1][0], 64, wmma::mem_row_major);
        wmma::store_matrix_sync(outs[m-1] + (size_t)node0 * 64 + 16, ah[m-1][1], 64, wmma::mem_row_major);
    }
}
template<int KP2, int NMAT>
static constexpr int proj_smem() {
    return (NMAT*32 + 128) * (KP2+8) * 2;
}

// ---------------- dst-centric edge aggregation (8 dst/warp, 4 lanes/dst) -------
__device__ __forceinline__ float edge_score(const uint4& kh, const float4& q0, const float4& q1) {
    float2 k0 = __half22float2(*(const __half2*)&kh.x);
    float2 k1 = __half22float2(*(const __half2*)&kh.y);
    float2 k2 = __half22float2(*(const __half2*)&kh.z);
    float2 k3 = __half22float2(*(const __half2*)&kh.w);
    return q0.x*k0.x + q0.y*k0.y + q0.z*k1.x + q0.w*k1.y
         + q1.x*k2.x + q1.y*k2.y + q1.z*k3.x + q1.w*k3.y;
}
__device__ __forceinline__ void edge_accum(unsigned long long acc[4], const uint4& vh, float ex) {
    unsigned long long ex2 = pack2(ex, ex);
    float2 v0 = __half22float2(*(const __half2*)&vh.x);
    float2 v1 = __half22float2(*(const __half2*)&vh.y);
    float2 v2 = __half22float2(*(const __half2*)&vh.z);
    float2 v3 = __half22float2(*(const __half2*)&vh.w);
    ffma2(acc[0], pack2(v0.x, v0.y), ex2);
    ffma2(acc[1], pack2(v1.x, v1.y), ex2);
    ffma2(acc[2], pack2(v2.x, v2.y), ex2);
    ffma2(acc[3], pack2(v3.x, v3.y), ex2);
}
__device__ __forceinline__ float accum_rel_h(int b0, int b1, const int* __restrict__ cs,
                                             const __half* __restrict__ kv,
                                             const float4& q0, const float4& q1,
                                             unsigned gmask, int ql,
                                             unsigned long long acc[4]) {
    float den = 0.f;
    int e = b0;
    for (; e + 4 <= b1; e += 4) {
        int s0 = __ldg(cs + e);
        int s1 = __ldg(cs + e + 1);
        int s2 = __ldg(cs + e + 2);
        int s3 = __ldg(cs + e + 3);
        const uint4* r0 = (const uint4*)(kv + (size_t)s0 * 64);
        const uint4* r1 = (const uint4*)(kv + (size_t)s1 * 64);
        const uint4* r2 = (const uint4*)(kv + (size_t)s2 * 64);
        const uint4* r3 = (const uint4*)(kv + (size_t)s3 * 64);
        uint4 k0 = __ldg(r0 + ql),     k1 = __ldg(r1 + ql);
        uint4 k2 = __ldg(r2 + ql),     k3 = __ldg(r3 + ql);
        uint4 v0 = __ldg(r0 + 4 + ql), v1 = __ldg(r1 + 4 + ql);
        uint4 v2 = __ldg(r2 + 4 + ql), v3 = __ldg(r3 + 4 + ql);
        float sc0 = edge_score(k0, q0, q1);
        float sc1 = edge_score(k1, q0, q1);
        float sc2 = edge_score(k2, q0, q1);
        float sc3 = edge_score(k3, q0, q1);
        sc0 += __shfl_xor_sync(gmask, sc0, 1);
        sc1 += __shfl_xor_sync(gmask, sc1, 1);
        sc2 += __shfl_xor_sync(gmask, sc2, 1);
        sc3 += __shfl_xor_sync(gmask, sc3, 1);
        sc0 += __shfl_xor_sync(gmask, sc0, 2);
        sc1 += __shfl_xor_sync(gmask, sc1, 2);
        sc2 += __shfl_xor_sync(gmask, sc2, 2);
        sc3 += __shfl_xor_sync(gmask, sc3, 2);
        float ex0 = __expf(fminf(sc0, 60.0f));
        float ex1 = __expf(fminf(sc1, 60.0f));
        float ex2 = __expf(fminf(sc2, 60.0f));
        float ex3 = __expf(fminf(sc3, 60.0f));
        edge_accum(acc, v0, ex0);
        edge_accum(acc, v1, ex1);
        edge_accum(acc, v2, ex2);
        edge_accum(acc, v3, ex3);
        den += (ex0 + ex1) + (ex2 + ex3);
    }
    if (e < b1) {
        int last = b1 - 1;
        int e1i = min(e + 1, last), e2i = min(e + 2, last), e3i = min(e + 3, last);
        int s0 = __ldg(cs + e);
        int s1 = __ldg(cs + e1i);
        int s2 = __ldg(cs + e2i);
        int s3 = __ldg(cs + e3i);
        const uint4* r0 = (const uint4*)(kv + (size_t)s0 * 64);
        const uint4* r1 = (const uint4*)(kv + (size_t)s1 * 64);
        const uint4* r2 = (const uint4*)(kv + (size_t)s2 * 64);
        const uint4* r3 = (const uint4*)(kv + (size_t)s3 * 64);
        uint4 k0 = __ldg(r0 + ql),     k1 = __ldg(r1 + ql);
        uint4 k2 = __ldg(r2 + ql),     k3 = __ldg(r3 + ql);
        uint4 v0 = __ldg(r0 + 4 + ql), v1 = __ldg(r1 + 4 + ql);
        uint4 v2 = __ldg(r2 + 4 + ql), v3 = __ldg(r3 + 4 + ql);
        float sc0 = edge_score(k0, q0, q1);
        float sc1 = edge_score(k1, q0, q1);
        float sc2 = edge_score(k2, q0, q1);
        float sc3 = edge_score(k3, q0, q1);
        sc0 += __shfl_xor_sync(gmask, sc0, 1);
        sc1 += __shfl_xor_sync(gmask, sc1, 1);
        sc2 += __shfl_xor_sync(gmask, sc2, 1);
        sc3 += __shfl_xor_sync(gmask, sc3, 1);
        sc0 += __shfl_xor_sync(gmask, sc0, 2);
        sc1 += __shfl_xor_sync(gmask, sc1, 2);
        sc2 += __shfl_xor_sync(gmask, sc2, 2);
        sc3 += __shfl_xor_sync(gmask, sc3, 2);
        float ex0 = __expf(fminf(sc0, 60.0f));
        float ex1 = (e + 1 < b1) ? __expf(fminf(sc1, 60.0f)) : 0.f;
        float ex2 = (e + 2 < b1) ? __expf(fminf(sc2, 60.0f)) : 0.f;
        float ex3 = (e + 3 < b1) ? __expf(fminf(sc3, 60.0f)) : 0.f;
        edge_accum(acc, v0, ex0);
        edge_accum(acc, v1, ex1);
        edge_accum(acc, v2, ex2);
        edge_accum(acc, v3, ex3);
        den += (ex0 + ex1) + (ex2 + ex3);
    }
    return den;
}
__global__ void agg1_kernel(const int* __restrict__ rp, const int* __restrict__ cs,
                            const float* __restrict__ q, const __half* __restrict__ kv,
                            float* __restrict__ xout, int n) {
    int gw   = (blockIdx.x * blockDim.x + threadIdx.x) >> 5;
    int lane = threadIdx.x & 31;
    int sub  = lane >> 2;
    int ql   = lane & 3;
    unsigned gmask = 0xFu << (sub * 4);
    int d = gw * 8 + sub;
    bool valid = (d < n);
    int dd = valid ? d : (n - 1);
    int b0 = __ldg(rp + dd);
    int b1 = valid ? __ldg(rp + dd + 1) : b0;
    float4 q0 = __ldg((const float4*)(q + (size_t)dd * 32) + ql * 2);
    float4 q1 = __ldg((const float4*)(q + (size_t)dd * 32) + ql * 2 + 1);
    unsigned long long acc[4];
    acc[0] = acc[1] = acc[2] = acc[3] = pack2(0.f, 0.f);
    float den = accum_rel_h(b0, b1, cs, kv, q0, q1, gmask, ql, acc);
    if (valid) {
        float inv = (den > 0.f) ? (1.0f / den) : 0.0f;
        float2 a0 = unpack2(acc[0]), a1 = unpack2(acc[1]);
        float2 a2 = unpack2(acc[2]), a3 = unpack2(acc[3]);
        *((float4*)(xout + (size_t)d * 32) + ql * 2)     = make_float4(a0.x*inv, a0.y*inv, a1.x*inv, a1.y*inv);
        *((float4*)(xout + (size_t)d * 32) + ql * 2 + 1) = make_float4(a2.x*inv, a2.y*inv, a3.x*inv, a3.y*inv);
    }
}
__global__ void agg2_kernel(const int* __restrict__ rp1, const int* __restrict__ cs1,
                            const __half* __restrict__ kvA,
                            const int* __restrict__ rp2, const int* __restrict__ cs2,
                            const __half* __restrict__ kvB,
                            const float* __restrict__ q,
                            float* __restrict__ xout, int n) {
    int gw   = (blockIdx.x * blockDim.x + threadIdx.x) >> 5;
    int lane = threadIdx.x & 31;
    int sub  = lane >> 2;
    int ql   = lane & 3;
    unsigned gmask = 0xFu << (sub * 4);
    int d = gw * 8 + sub;
    bool valid = (d < n);
    int dd = valid ? d : (n - 1);
    float4 q0 = __ldg((const float4*)(q + (size_t)dd * 32) + ql * 2);
    float4 q1 = __ldg((const float4*)(q + (size_t)dd * 32) + ql * 2 + 1);
    int a0 = __ldg(rp1 + dd);
    int a1 = valid ? __ldg(rp1 + dd + 1) : a0;
    int c0 = __ldg(rp2 + dd);
    int c1 = valid ? __ldg(rp2 + dd + 1) : c0;
    unsigned long long accA[4], accB[4];
    accA[0]=accA[1]=accA[2]=accA[3]=pack2(0.f,0.f);
    accB[0]=accB[1]=accB[2]=accB[3]=pack2(0.f,0.f);
    float denA = accum_rel_h(a0, a1, cs1, kvA, q0, q1, gmask, ql, accA);
    float denB = accum_rel_h(c0, c1, cs2, kvB, q0, q1, gmask, ql, accB);
    if (valid) {
        float invA = (denA > 0.f) ? (1.0f / denA) : 0.0f;
        float invB = (denB > 0.f) ? (1.0f / denB) : 0.0f;
        float2 rA[4], rB[4];
#pragma unroll
        for (int i = 0; i < 4; i++) { rA[i] = unpack2(accA[i]); rB[i] = unpack2(accB[i]); }
        *((float4*)(xout + (size_t)d * 32) + ql * 2) =
            make_float4(rA[0].x*invA + rB[0].x*invB, rA[0].y*invA + rB[0].y*invB,
                        rA[1].x*invA + rB[1].x*invB, rA[1].y*invA + rB[1].y*invB);
        *((float4*)(xout + (size_t)d * 32) + ql * 2 + 1) =
            make_float4(rA[2].x*invA + rB[2].x*invB, rA[2].y*invA + rB[2].y*invB,
                        rA[3].x*invA + rB[3].x*invB, rA[3].y*invA + rB[3].y*invB);
    }
}

// ---------------- output transform ---------------------------------------------
// out16 (optional): fp16 copy at stride KP2_L2=48 with ones column at col 32.
__global__ void out_kernel(const float* __restrict__ x1,
                           const float* __restrict__ Wa, const float* __restrict__ ba,
                           const float* __restrict__ skipv, int t_idx,
                           const float* __restrict__ xin,
                           float* __restrict__ out, __half* __restrict__ out16,
                           int n, int use_skip) {
    __shared__ float sW[1024];
    for (int i = threadIdx.x; i < 1024; i += blockDim.x) sW[i] = Wa[i];
    __syncthreads();
    int lane = threadIdx.x & 31;
    int gw = blockIdx.x * (blockDim.x >> 5) + (threadIdx.x >> 5);
    int n0 = gw * 4;
    if (n0 >= n) return;
    int m = n - n0; if (m > 4) m = 4;

    float4 xr[4];
#pragma unroll
    for (int j = 0; j < 4; j++) {
        if (j < m && lane < 8) {
            float4 a = __ldg((const float4*)(x1 + (size_t)(n0 + j) * 32) + lane);
            a.x = 0.5f * a.x * (1.0f + erff(a.x * 0.7071067811865475f));
            a.y = 0.5f * a.y * (1.0f + erff(a.y * 0.7071067811865475f));
            a.z = 0.5f * a.z * (1.0f + erff(a.z * 0.7071067811865475f));
            a.w = 0.5f * a.w * (1.0f + erff(a.w * 0.7071067811865475f));
            xr[j] = a;
        } else {
            xr[j] = make_float4(0.f, 0.f, 0.f, 0.f);
        }
    }
    unsigned long long A01 = pack2(ba[lane], ba[lane]), A23 = A01;
    for (int i0 = 0; i0 < 32; i0 += 4) {
        int sl = i0 >> 2;
        float xs[4][4];
#pragma unroll
        for (int j = 0; j < 4; j++) {
            xs[j][0] = __shfl_sync(0xffffffffu, xr[j].x, sl);
            xs[j][1] = __shfl_sync(0xffffffffu, xr[j].y, sl);
            xs[j][2] = __shfl_sync(0xffffffffu, xr[j].z, sl);
            xs[j][3] = __shfl_sync(0xffffffffu, xr[j].w, sl);
        }
#pragma unroll
        for (int c = 0; c < 4; c++) {
            float w = sW[(i0 + c) * 32 + lane];
            unsigned long long w2 = pack2(w, w);
            ffma2(A01, pack2(xs[0][c], xs[1][c]), w2);
            ffma2(A23, pack2(xs[2][c], xs[3][c]), w2);
        }
    }
    float2 a01 = unpack2(A01), a23 = unpack2(A23);
    float o[4] = {a01.x, a01.y, a23.x, a23.y};
    if (use_skip) {
        float a = 1.0f / (1.0f + expf(-__ldg(skipv + t_idx)));
#pragma unroll
        for (int j = 0; j < 4; j++) {
            if (j < m)
                o[j] = a * o[j] + (1.0f - a) * __ldg(xin + (size_t)(n0 + j) * 32 + lane);
        }
    }
#pragma unroll
    for (int j = 0; j < 4; j++) {
        if (j < m) {
            out[(size_t)(n0 + j) * 32 + lane] = o[j];
            if (out16) {
                out16[(size_t)(n0 + j) * KP2_L2 + lane] = __float2half(o[j]);
                if (lane < 16)
                    out16[(size_t)(n0 + j) * KP2_L2 + 32 + lane] =
                        __float2half(lane == 0 ? 1.0f : 0.0f);
            }
        }
    }
}

// ---------------- host orchestration ----------------------------------------
struct LayerW {
    const float *Wk, *bk, *Wq, *bq, *Wv, *bv, *Wa, *ba, *skip, *arel, *mrel, *prel;
};

template<int KP2, bool F32IN>
static void run_proj(const void* xa_in, const void* xp_in, int F,
                     const LayerW& L,
                     float* qa, float* qp,
                     __half* kv0, __half* kv1, __half* kv2,
                     __half* Wt) {
    const int BT = 256;
    int wsz = F * 32;
    CArgs ca;
    ca.prel = L.prel;
    ca.t[0] = { L.Wq,       L.bq,      (const float*)0, -1 };
    ca.t[1] = { L.Wk,       L.bk,      L.arel + 0,      0  };
    ca.t[2] = { L.Wv,       L.bv,      L.mrel + 0,      -1 };
    ca.t[3] = { L.Wq + wsz, L.bq + 32, (const float*)0, -1 };
    ca.t[4] = { L.Wk + wsz, L.bk + 32, L.arel + 1024,   1  };
    ca.t[5] = { L.Wv + wsz, L.bv + 32, L.mrel + 1024,   -1 };
    ca.t[6] = { L.Wk + wsz, L.bk + 32, L.arel + 2048,   2  };
    ca.t[7] = { L.Wv + wsz, L.bv + 32, L.mrel + 2048,   -1 };
    dim3 cg(divup(KP2 * 32, BT), 8);
    compose_all_kernel<<<cg, BT>>>(ca, F, KP2, Wt);

    proj_wmma_kernel<KP2, 5, F32IN><<<divup(NP_, 128), 256, proj_smem<KP2,5>()>>>(
        xp_in, Wt + (size_t)3 * 32 * KP2, qp,
        kv1, kv1 + 32, kv2, kv2 + 32, NP_);
    proj_wmma_kernel<KP2, 3, F32IN><<<divup(NA_, 128), 256, proj_smem<KP2,3>()>>>(
        xa_in, Wt, qa, kv0, kv0 + 32, (__half*)0, (__half*)0, NA_);
}

static void run_agg_out(const LayerW& L, int use_skip,
                        const float* xa_skip, const float* xp_skip,
                        float* outa, float* outp, __half* outa16, __half* outp16,
                        float* qa, float* qp,
                        __half* kv0, __half* kv1, __half* kv2,
                        float* xa_agg, float* xp_agg,
                        const int* rp_w, const int* cs_w,
                        const int* rp_b, const int* cs_b,
                        const int* rp_c, const int* cs_c) {
    const int BT = 256;
    int gaA = divup(NA_, 64), gpA = divup(NP_, 64);
    agg2_kernel<<<gpA, BT>>>(rp_w, cs_w, kv0, rp_c, cs_c, kv2, qp, xp_agg, NP_);
    agg1_kernel<<<gaA, BT>>>(rp_b, cs_b, qa, kv1, xa_agg, NA_);

    int ga4 = divup(divup(NA_, 4) * 32, BT);
    int gp4 = divup(divup(NP_, 4) * 32, BT);
    out_kernel<<<ga4, BT>>>(xa_agg, L.Wa,        L.ba,      L.skip, 0, xa_skip, outa, outa16, NA_, use_skip);
    out_kernel<<<gp4, BT>>>(xp_agg, L.Wa + 1024, L.ba + 32, L.skip, 1, xp_skip, outp, outp16, NP_, use_skip);
}

extern "C" void kernel_launch(void* const* d_in, const int* in_sizes, int n_in,
                              void* d_out, int out_size) {
    const float* x_a   = (const float*)d_in[0];
    const float* x_p   = (const float*)d_in[1];
    const int* e_wr    = (const int*)d_in[2];
    const int* e_wb    = (const int*)d_in[3];
    const int* e_ci    = (const int*)d_in[4];
    LayerW L1 = { (const float*)d_in[5],  (const float*)d_in[6],
                  (const float*)d_in[7],  (const float*)d_in[8],
                  (const float*)d_in[9],  (const float*)d_in[10],
                  (const float*)d_in[11], (const float*)d_in[12],
                  (const float*)d_in[13], (const float*)d_in[14],
                  (const float*)d_in[15], (const float*)d_in[16] };
    LayerW L2 = { (const float*)d_in[17], (const float*)d_in[18],
                  (const float*)d_in[19], (const float*)d_in[20],
                  (const float*)d_in[21], (const float*)d_in[22],
                  (const float*)d_in[23], (const float*)d_in[24],
                  (const float*)d_in[25], (const float*)d_in[26],
                  (const float*)d_in[27], (const float*)d_in[28] };

    float *qa,*qp,*xa_agg,*xp_agg,*h1a,*h1p;
    __half *kv0,*kv1,*kv2,*x16a,*x16p,*Wt;
    cudaGetSymbolAddress((void**)&qa, g_qa);   cudaGetSymbolAddress((void**)&qp, g_qp);
    cudaGetSymbolAddress((void**)&kv0, g_kv0);
    cudaGetSymbolAddress((void**)&kv1, g_kv1);
    cudaGetSymbolAddress((void**)&kv2, g_kv2);
    cudaGetSymbolAddress((void**)&xa_agg, g_xa);
    cudaGetSymbolAddress((void**)&xp_agg, g_xp);
    cudaGetSymbolAddress((void**)&h1a, g_h1a); cudaGetSymbolAddress((void**)&h1p, g_h1p);
    cudaGetSymbolAddress((void**)&x16a, g_x16a); cudaGetSymbolAddress((void**)&x16p, g_x16p);
    cudaGetSymbolAddress((void**)&Wt, g_Wt);

    Rel3 R;
    R.e0 = e_ci; R.E0 = EC_;  R.n0 = NP_;
    R.e1 = e_wr; R.E1 = EW_;  R.n1 = NP_;
    R.e2 = e_wb; R.E2 = EWB_; R.n2 = NA_;
    cudaGetSymbolAddress((void**)&R.deg0, g_deg_c); cudaGetSymbolAddress((void**)&R.rp0, g_rp_c);
    cudaGetSymbolAddress((void**)&R.cs0, g_cs_c);   cudaGetSymbolAddress((void**)&R.bs0, g_bs_c);
    cudaGetSymbolAddress((void**)&R.deg1, g_deg_w); cudaGetSymbolAddress((void**)&R.rp1, g_rp_w);
    cudaGetSymbolAddress((void**)&R.cs1, g_cs_w);   cudaGetSymbolAddress((void**)&R.bs1, g_bs_w);
    cudaGetSymbolAddress((void**)&R.deg2, g_deg_b); cudaGetSymbolAddress((void**)&R.rp2, g_rp_b);
    cudaGetSymbolAddress((void**)&R.cs2, g_cs_b);   cudaGetSymbolAddress((void**)&R.bs2, g_bs_b);

    cudaFuncSetAttribute(proj_wmma_kernel<KP2_L1,3,true>, cudaFuncAttributeMaxDynamicSharedMemorySize,
                         proj_smem<KP2_L1,3>());
    cudaFuncSetAttribute(proj_wmma_kernel<KP2_L1,5,true>, cudaFuncAttributeMaxDynamicSharedMemorySize,
                         proj_smem<KP2_L1,5>());
    cudaFuncSetAttribute(proj_wmma_kernel<KP2_L2,3,false>, cudaFuncAttributeMaxDynamicSharedMemorySize,
                         proj_smem<KP2_L2,3>());
    cudaFuncSetAttribute(proj_wmma_kernel<KP2_L2,5,false>, cudaFuncAttributeMaxDynamicSharedMemorySize,
                         proj_smem<KP2_L2,5>());

    const int BT = 256;
    int totE = EC_ + EW_ + EWB_;
    int totN = NP_ + NP_ + NA_;
    int nbmax = divup(NP_, 1024);

    // Order: zero(1), count(2), compose(3), proj_p(4 <- ncu slot), proj_a,
    //        scans, scatter, aggs, outs, layer 2.
    zero_all_kernel<<<divup(totN, BT), BT>>>(R);
    count_all_kernel<<<divup(totE, BT), BT>>>(R);
    run_proj<KP2_L1, true>(x_a, x_p, 128, L1, qa, qp, kv0, kv1, kv2, Wt);

    scan_p1_all<<<dim3(nbmax, 3), 256>>>(R);
    scan_p2_all<<<3, 256>>>(R);
    scan_p3_all<<<dim3(nbmax, 3), 256>>>(R);
    scatter_all_kernel<<<divup(totE, BT), BT>>>(R);

    // Layer 1 agg + out (emits fp16 copy with ones column for layer 2 input)
    run_agg_out(L1, 0, x_a, x_p, h1a, h1p, x16a, x16p,
                qa, qp, kv0, kv1, kv2, xa_agg, xp_agg,
                R.rp1, R.cs1, R.rp2, R.cs2, R.rp0, R.cs0);

    // Layer 2: 32 -> 32, gated skip.
    run_proj<KP2_L2, false>(x16a, x16p, 32, L2, qa, qp, kv0, kv1, kv2, Wt);
    float* out = (float*)d_out;
    run_agg_out(L2, 1, h1a, h1p, out, out + (size_t)NA_ * 32, (__half*)0, (__half*)0,
                qa, qp, kv0, kv1, kv2, xa_agg, xp_agg,
                R.rp1, R.cs1, R.rp2, R.cs2, R.rp0, R.cs0);
}

// round 17
// speedup vs baseline: 1.3818x; 1.0297x over previous
#include <cuda_runtime.h>
#include <cuda_fp16.h>
#include <mma.h>
#include <math.h>
#include <stdint.h>

#define NA_  100000
#define NP_  200000
#define EW_  1000000
#define EWB_ 1000000
#define EC_  2000000
#define KP2_L1 144   // 128 + 16 (ones/bias column block)
#define KP2_L2 48    // 32 + 16

// ---------------- scratch (device globals; no allocation allowed) ----------
__device__ float g_qa[(NA_+128)*32], g_qp[(NP_+128)*32];
__device__ __align__(32) __half g_kv0[(NA_+128)*64];   // authors as src (writes)
__device__ __align__(32) __half g_kv1[(NP_+128)*64];   // papers as src (written_by)
__device__ __align__(32) __half g_kv2[(NP_+128)*64];   // papers as src (cites)
__device__ float g_xa[NA_*32], g_xp[NP_*32];
__device__ float g_h1a[NA_*32], g_h1p[NP_*32];
__device__ __align__(32) __half g_x16a[NA_*KP2_L2], g_x16p[NP_*KP2_L2];
// CSR per relation (dst-indexed)
__device__ int g_deg_w[NP_], g_rp_w[NP_+1];  __device__ int g_cs_w[EW_];
__device__ int g_deg_b[NA_], g_rp_b[NA_+1];  __device__ int g_cs_b[EWB_];
__device__ int g_deg_c[NP_], g_rp_c[NP_+1];  __device__ int g_cs_c[EC_];
__device__ int g_bs_w[256], g_bs_b[256], g_bs_c[256];
// composite weights: 8 tasks x [32][KP2<=144] fp16 (col-major B, bias at row F)
__device__ __align__(32) __half g_Wt[8*32*KP2_L1];

// ---------------- helpers ---------------------------------------------------
__device__ __forceinline__ unsigned long long pack2(float lo, float hi) {
    unsigned long long r;
    asm("mov.b64 %0, {%1,%2};" : "=l"(r) : "f"(lo), "f"(hi));
    return r;
}
__device__ __forceinline__ void ffma2(unsigned long long& acc,
                                      unsigned long long a, unsigned long long b) {
    asm("fma.rn.f32x2 %0, %1, %2, %0;" : "+l"(acc) : "l"(a), "l"(b));
}
__device__ __forceinline__ float2 unpack2(unsigned long long v) {
    float2 r;
    asm("mov.b64 {%0,%1}, %2;" : "=f"(r.x), "=f"(r.y) : "l"(v));
    return r;
}
static inline int divup(int a, int b) { return (a + b - 1) / b; }

// ---------------- fused CSR build ----------------------------------------------
struct Rel3 {
    const int *e0, *e1, *e2;
    int E0, E1, E2;
    int n0, n1, n2;
    int *deg0, *deg1, *deg2;
    int *rp0, *rp1, *rp2;
    int *cs0, *cs1, *cs2;
    int *bs0, *bs1, *bs2;
};

__global__ void zero_all_kernel(Rel3 R) {
    int i = blockIdx.x * blockDim.x + threadIdx.x;
    int t = R.n0 + R.n1 + R.n2;
    if (i >= t) return;
    if (i < R.n0) R.deg0[i] = 0;
    else if (i < R.n0 + R.n1) R.deg1[i - R.n0] = 0;
    else R.deg2[i - R.n0 - R.n1] = 0;
}
__global__ void count_all_kernel(Rel3 R) {
    int i = blockIdx.x * blockDim.x + threadIdx.x;
    if (i < R.E0) { atomicAdd(&R.deg0[__ldg(R.e0 + R.E0 + i)], 1); return; }
    i -= R.E0;
    if (i < R.E1) { atomicAdd(&R.deg1[__ldg(R.e1 + R.E1 + i)], 1); return; }
    i -= R.E1;
    if (i < R.E2) { atomicAdd(&R.deg2[__ldg(R.e2 + R.E2 + i)], 1); }
}
__device__ __forceinline__ void rel_sel(const Rel3& R, int r, const int*& deg, int& n, int*& bsum) {
    if (r == 0) { deg = R.deg0; n = R.n0; bsum = R.bs0; }
    else if (r == 1) { deg = R.deg1; n = R.n1; bsum = R.bs1; }
    else { deg = R.deg2; n = R.n2; bsum = R.bs2; }
}
__global__ void scan_p1_all(Rel3 R) {
    const int* deg; int n; int* bsum;
    rel_sel(R, blockIdx.y, deg, n, bsum);
    int base = blockIdx.x * 1024;
    if (base >= n) return;
    __shared__ int sm[256];
    int t = threadIdx.x;
    int s = 0;
#pragma unroll
    for (int j = 0; j < 4; j++) {
        int i = base + t * 4 + j;
        if (i < n) s += deg[i];
    }
    sm[t] = s; __syncthreads();
#pragma unroll
    for (int o = 128; o > 0; o >>= 1) {
        if (t < o) sm[t] += sm[t + o];
        __syncthreads();
    }
    if (t == 0) bsum[blockIdx.x] = sm[0];
}
__global__ void scan_p2_all(Rel3 R) {
    const int* degc; int n; int* bsum;
    rel_sel(R, blockIdx.x, degc, n, bsum);
    int* rp_last = (blockIdx.x == 0 ? R.rp0 : blockIdx.x == 1 ? R.rp1 : R.rp2) + n;
    int nb = (n + 1023) / 1024;
    __shared__ int sm[256];
    int t = threadIdx.x;
    int v = (t < nb) ? bsum[t] : 0;
    sm[t] = v; __syncthreads();
    for (int o = 1; o < 256; o <<= 1) {
        int x = (t >= o) ? sm[t - o] : 0;
        __syncthreads();
        sm[t] += x;
        __syncthreads();
    }
    if (t < nb) bsum[t] = sm[t] - v;
    if (t == 255) *rp_last = sm[255];
}
__global__ void scan_p3_all(Rel3 R) {
    const int* deg; int n; int* bsum;
    rel_sel(R, blockIdx.y, deg, n, bsum);
    int* rp  = (blockIdx.y == 0 ? R.rp0  : blockIdx.y == 1 ? R.rp1  : R.rp2);
    int* cur = (blockIdx.y == 0 ? R.deg0 : blockIdx.y == 1 ? R.deg1 : R.deg2);
    int base = blockIdx.x * 1024;
    if (base >= n) return;
    __shared__ int sm[256];
    int t = threadIdx.x;
    int v[4]; int s = 0;
#pragma unroll
    for (int j = 0; j < 4; j++) {
        int i = base + t * 4 + j;
        v[j] = (i < n) ? deg[i] : 0;
        s += v[j];
    }
    sm[t] = s; __syncthreads();
    for (int o = 1; o < 256; o <<= 1) {
        int x = (t >= o) ? sm[t - o] : 0;
        __syncthreads();
        sm[t] += x;
        __syncthreads();
    }
    int run = bsum[blockIdx.x] + sm[t] - s;
#pragma unroll
    for (int j = 0; j < 4; j++) {
        int i = base + t * 4 + j;
        if (i < n) { rp[i] = run; cur[i] = run; }
        run += v[j];
    }
}
__global__ void scatter_all_kernel(Rel3 R) {
    int i = blockIdx.x * blockDim.x + threadIdx.x;
    const int* e; int E; int* cur; int* cs;
    if (i < R.E0) { e = R.e0; E = R.E0; cur = R.deg0; cs = R.cs0; }
    else {
        i -= R.E0;
        if (i < R.E1) { e = R.e1; E = R.E1; cur = R.deg1; cs = R.cs1; }
        else {
            i -= R.E1;
            if (i >= R.E2) return;
            e = R.e2; E = R.E2; cur = R.deg2; cs = R.cs2;
        }
    }
    int slot = atomicAdd(&cur[__ldg(e + E + i)], 1);
    cs[slot] = __ldg(e + i);
}

// ---------------- weight composition (all 8 tasks, one launch) -----------------
struct CTask { const float* W; const float* b; const float* T; int prel_idx; };
struct CArgs { CTask t[8]; const float* prel; };

__global__ void compose_all_kernel(CArgs args, int F, int KP2, __half* __restrict__ Wt) {
    int task = blockIdx.y;
    int gw   = (blockIdx.x * blockDim.x + threadIdx.x) >> 5;
    int lane = threadIdx.x & 31;
    if (gw >= KP2) return;
    CTask tk = args.t[task];
    __half* dst = &Wt[((size_t)task * 32 + lane) * KP2 + gw];
    if (gw > F) { *dst = __float2half(0.f); return; }
    float scale = (tk.prel_idx >= 0) ? (__ldg(args.prel + tk.prel_idx) * 0.17677669529663687f) : 1.0f;
    float rv = (gw == F) ? tk.b[lane] : tk.W[(size_t)gw * 32 + lane];
    float acc;
    if (tk.T) {
        acc = 0.f;
#pragma unroll
        for (int j = 0; j < 32; j++) {
            float rj = __shfl_sync(0xffffffffu, rv, j);
            acc = fmaf(rj, __ldg(tk.T + j * 32 + lane), acc);
        }
    } else acc = rv;
    *dst = __float2half(acc * scale);
}

// ---------------- wmma (HMMA) projection — direct-store, bias-folded ------------
template<int KP2, int NMAT, bool F32IN>
__global__ void __launch_bounds__(256) proj_wmma_kernel(
        const void* __restrict__ xin, const __half* __restrict__ Wt,
        float* __restrict__ qout,
        __half* __restrict__ o1, __half* __restrict__ o2,
        __half* __restrict__ o3, __half* __restrict__ o4, int n) {
    extern __shared__ __align__(32) __half smem_h[];
    const int LD = KP2 + 8;
    const int F = KP2 - 16;
    __half* sB = smem_h;
    __half* sA = sB + NMAT * 32 * LD;
    int tid = threadIdx.x, wid = tid >> 5;
    int base = blockIdx.x * 128;
    const int CH = KP2 / 8;
    for (int idx = tid; idx < NMAT * 32 * CH; idx += 256) {
        int r = idx / CH, c8 = (idx % CH) * 8;
        *(uint4*)(sB + r * LD + c8) = *(const uint4*)(Wt + (size_t)r * KP2 + c8);
    }
    for (int idx = tid; idx < 128 * CH; idx += 256) {
        int row = idx / CH, c8 = (idx % CH) * 8;
        bool rv = (base + row < n);
        if (F32IN) {
            __half2 h[4];
            if (rv && c8 < F) {
                const float4* xr = (const float4*)((const float*)xin + (size_t)(base + row) * F + c8);
                float4 a = __ldg(xr), b = __ldg(xr + 1);
                h[0] = __floats2half2_rn(a.x, a.y);
                h[1] = __floats2half2_rn(a.z, a.w);
                h[2] = __floats2half2_rn(b.x, b.y);
                h[3] = __floats2half2_rn(b.z, b.w);
            } else {
                float one = (rv && c8 == F) ? 1.0f : 0.0f;
                h[0] = __floats2half2_rn(one, 0.f);
                h[1] = h[2] = h[3] = __floats2half2_rn(0.f, 0.f);
            }
            *(uint4*)(sA + row * LD + c8) = *(uint4*)h;
        } else {
            uint4 v = make_uint4(0, 0, 0, 0);
            if (rv) v = *(const uint4*)((const __half*)xin + (size_t)(base + row) * KP2 + c8);
            *(uint4*)(sA + row * LD + c8) = v;
        }
    }
    __syncthreads();

    using namespace nvcuda;
    int m0 = wid * 16;
    int node0 = base + m0;
    wmma::fragment<wmma::accumulator, 16, 16, 16, float> q0f, q1f;
    wmma::fill_fragment(q0f, 0.f);
    wmma::fill_fragment(q1f, 0.f);
    wmma::fragment<wmma::accumulator, 16, 16, 16, __half> ah[NMAT-1][2];
#pragma unroll
    for (int m = 0; m < NMAT-1; m++) {
        wmma::fill_fragment(ah[m][0], __float2half(0.f));
        wmma::fill_fragment(ah[m][1], __float2half(0.f));
    }

#pragma unroll
    for (int k0 = 0; k0 < KP2; k0 += 16) {
        wmma::fragment<wmma::matrix_a, 16, 16, 16, __half, wmma::row_major> fa;
        wmma::load_matrix_sync(fa, sA + m0 * LD + k0, LD);
        {
            wmma::fragment<wmma::matrix_b, 16, 16, 16, __half, wmma::col_major> fb0, fb1;
            wmma::load_matrix_sync(fb0, sB + k0, LD);
            wmma::load_matrix_sync(fb1, sB + 16 * LD + k0, LD);
            wmma::mma_sync(q0f, fa, fb0, q0f);
            wmma::mma_sync(q1f, fa, fb1, q1f);
        }
#pragma unroll
        for (int m = 1; m < NMAT; m++) {
            wmma::fragment<wmma::matrix_b, 16, 16, 16, __half, wmma::col_major> fb0, fb1;
            const __half* Bm = sB + m * 32 * LD;
            wmma::load_matrix_sync(fb0, Bm + k0, LD);
            wmma::load_matrix_sync(fb1, Bm + 16 * LD + k0, LD);
            wmma::mma_sync(ah[m-1][0], fa, fb0, ah[m-1][0]);
            wmma::mma_sync(ah[m-1][1], fa, fb1, ah[m-1][1]);
        }
    }
    wmma::store_matrix_sync(qout + (size_t)node0 * 32,      q0f, 32, wmma::mem_row_major);
    wmma::store_matrix_sync(qout + (size_t)node0 * 32 + 16, q1f, 32, wmma::mem_row_major);
    __half* outs[4] = {o1, o2, o3, o4};
#pragma unroll
    for (int m = 1; m < NMAT; m++) {
        wmma::store_matrix_sync(outs[m-1] + (size_t)node0 * 64,      ah[m-1][0], 64, wmma::mem_row_major);
        wmma::store_matrix_sync(outs[m-1] + (size_t)node0 * 64 + 16, ah[m-1][1], 64, wmma::mem_row_major);
    }
}
template<int KP2, int NMAT>
static constexpr int proj_smem() {
    return (NMAT*32 + 128) * (KP2+8) * 2;
}

// ---------------- dst-centric edge aggregation (8 dst/warp, 4 lanes/dst) -------
__device__ __forceinline__ float edge_score(const uint4& kh, const float4& q0, const float4& q1) {
    float2 k0 = __half22float2(*(const __half2*)&kh.x);
    float2 k1 = __half22float2(*(const __half2*)&kh.y);
    float2 k2 = __half22float2(*(const __half2*)&kh.z);
    float2 k3 = __half22float2(*(const __half2*)&kh.w);
    return q0.x*k0.x + q0.y*k0.y + q0.z*k1.x + q0.w*k1.y
         + q1.x*k2.x + q1.y*k2.y + q1.z*k3.x + q1.w*k3.y;
}
__device__ __forceinline__ void edge_accum(unsigned long long acc[4], const uint4& vh, float ex) {
    unsigned long long ex2 = pack2(ex, ex);
    float2 v0 = __half22float2(*(const __half2*)&vh.x);
    float2 v1 = __half22float2(*(const __half2*)&vh.y);
    float2 v2 = __half22float2(*(const __half2*)&vh.z);
    float2 v3 = __half22float2(*(const __half2*)&vh.w);
    ffma2(acc[0], pack2(v0.x, v0.y), ex2);
    ffma2(acc[1], pack2(v1.x, v1.y), ex2);
    ffma2(acc[2], pack2(v2.x, v2.y), ex2);
    ffma2(acc[3], pack2(v3.x, v3.y), ex2);
}
__device__ __forceinline__ float accum_rel_h(int b0, int b1, const int* __restrict__ cs,
                                             const __half* __restrict__ kv,
                                             const float4& q0, const float4& q1,
                                             unsigned gmask, int ql,
                                             unsigned long long acc[4]) {
    float den = 0.f;
    int e = b0;
    for (; e + 4 <= b1; e += 4) {
        int s0 = __ldg(cs + e);
        int s1 = __ldg(cs + e + 1);
        int s2 = __ldg(cs + e + 2);
        int s3 = __ldg(cs + e + 3);
        const uint4* r0 = (const uint4*)(kv + (size_t)s0 * 64);
        const uint4* r1 = (const uint4*)(kv + (size_t)s1 * 64);
        const uint4* r2 = (const uint4*)(kv + (size_t)s2 * 64);
        const uint4* r3 = (const uint4*)(kv + (size_t)s3 * 64);
        uint4 k0 = __ldg(r0 + ql),     k1 = __ldg(r1 + ql);
        uint4 k2 = __ldg(r2 + ql),     k3 = __ldg(r3 + ql);
        uint4 v0 = __ldg(r0 + 4 + ql), v1 = __ldg(r1 + 4 + ql);
        uint4 v2 = __ldg(r2 + 4 + ql), v3 = __ldg(r3 + 4 + ql);
        float sc0 = edge_score(k0, q0, q1);
        float sc1 = edge_score(k1, q0, q1);
        float sc2 = edge_score(k2, q0, q1);
        float sc3 = edge_score(k3, q0, q1);
        sc0 += __shfl_xor_sync(gmask, sc0, 1);
        sc1 += __shfl_xor_sync(gmask, sc1, 1);
        sc2 += __shfl_xor_sync(gmask, sc2, 1);
        sc3 += __shfl_xor_sync(gmask, sc3, 1);
        sc0 += __shfl_xor_sync(gmask, sc0, 2);
        sc1 += __shfl_xor_sync(gmask, sc1, 2);
        sc2 += __shfl_xor_sync(gmask, sc2, 2);
        sc3 += __shfl_xor_sync(gmask, sc3, 2);
        float ex0 = __expf(fminf(sc0, 60.0f));
        float ex1 = __expf(fminf(sc1, 60.0f));
        float ex2 = __expf(fminf(sc2, 60.0f));
        float ex3 = __expf(fminf(sc3, 60.0f));
        edge_accum(acc, v0, ex0);
        edge_accum(acc, v1, ex1);
        edge_accum(acc, v2, ex2);
        edge_accum(acc, v3, ex3);
        den += (ex0 + ex1) + (ex2 + ex3);
    }
    if (e < b1) {
        int last = b1 - 1;
        int e1i = min(e + 1, last), e2i = min(e + 2, last), e3i = min(e + 3, last);
        int s0 = __ldg(cs + e);
        int s1 = __ldg(cs + e1i);
        int s2 = __ldg(cs + e2i);
        int s3 = __ldg(cs + e3i);
        const uint4* r0 = (const uint4*)(kv + (size_t)s0 * 64);
        const uint4* r1 = (const uint4*)(kv + (size_t)s1 * 64);
        const uint4* r2 = (const uint4*)(kv + (size_t)s2 * 64);
        const uint4* r3 = (const uint4*)(kv + (size_t)s3 * 64);
        uint4 k0 = __ldg(r0 + ql),     k1 = __ldg(r1 + ql);
        uint4 k2 = __ldg(r2 + ql),     k3 = __ldg(r3 + ql);
        uint4 v0 = __ldg(r0 + 4 + ql), v1 = __ldg(r1 + 4 + ql);
        uint4 v2 = __ldg(r2 + 4 + ql), v3 = __ldg(r3 + 4 + ql);
        float sc0 = edge_score(k0, q0, q1);
        float sc1 = edge_score(k1, q0, q1);
        float sc2 = edge_score(k2, q0, q1);
        float sc3 = edge_score(k3, q0, q1);
        sc0 += __shfl_xor_sync(gmask, sc0, 1);
        sc1 += __shfl_xor_sync(gmask, sc1, 1);
        sc2 += __shfl_xor_sync(gmask, sc2, 1);
        sc3 += __shfl_xor_sync(gmask, sc3, 1);
        sc0 += __shfl_xor_sync(gmask, sc0, 2);
        sc1 += __shfl_xor_sync(gmask, sc1, 2);
        sc2 += __shfl_xor_sync(gmask, sc2, 2);
        sc3 += __shfl_xor_sync(gmask, sc3, 2);
        float ex0 = __expf(fminf(sc0, 60.0f));
        float ex1 = (e + 1 < b1) ? __expf(fminf(sc1, 60.0f)) : 0.f;
        float ex2 = (e + 2 < b1) ? __expf(fminf(sc2, 60.0f)) : 0.f;
        float ex3 = (e + 3 < b1) ? __expf(fminf(sc3, 60.0f)) : 0.f;
        edge_accum(acc, v0, ex0);
        edge_accum(acc, v1, ex1);
        edge_accum(acc, v2, ex2);
        edge_accum(acc, v3, ex3);
        den += (ex0 + ex1) + (ex2 + ex3);
    }
    return den;
}

// Fused: paper blocks [0, gpA) do 2-relation agg; author blocks [gpA, ..) 1-rel.
struct AggArgs {
    const int *rp_w, *cs_w, *rp_c, *cs_c, *rp_b, *cs_b;
    const __half *kv0, *kv2, *kv1;
    const float *qp, *qa;
    float *xp_agg, *xa_agg;
    int gpA;
};
__global__ void agg_all_kernel(AggArgs A) {
    int lane = threadIdx.x & 31;
    int sub  = lane >> 2;
    int ql   = lane & 3;
    unsigned gmask = 0xFu << (sub * 4);
    bool isP = (blockIdx.x < (unsigned)A.gpA);
    int blk = isP ? blockIdx.x : (blockIdx.x - A.gpA);
    int gw = blk * (blockDim.x >> 5) + (threadIdx.x >> 5);
    int d = gw * 8 + sub;
    if (isP) {
        bool valid = (d < NP_);
        int dd = valid ? d : (NP_ - 1);
        const float* q = A.qp;
        float4 q0 = __ldg((const float4*)(q + (size_t)dd * 32) + ql * 2);
        float4 q1 = __ldg((const float4*)(q + (size_t)dd * 32) + ql * 2 + 1);
        int a0 = __ldg(A.rp_w + dd);
        int a1 = valid ? __ldg(A.rp_w + dd + 1) : a0;
        int c0 = __ldg(A.rp_c + dd);
        int c1 = valid ? __ldg(A.rp_c + dd + 1) : c0;
        unsigned long long accA[4], accB[4];
        accA[0]=accA[1]=accA[2]=accA[3]=pack2(0.f,0.f);
        accB[0]=accB[1]=accB[2]=accB[3]=pack2(0.f,0.f);
        float denA = accum_rel_h(a0, a1, A.cs_w, A.kv0, q0, q1, gmask, ql, accA);
        float denB = accum_rel_h(c0, c1, A.cs_c, A.kv2, q0, q1, gmask, ql, accB);
        if (valid) {
            float invA = (denA > 0.f) ? (1.0f / denA) : 0.0f;
            float invB = (denB > 0.f) ? (1.0f / denB) : 0.0f;
            float2 rA[4], rB[4];
#pragma unroll
            for (int i = 0; i < 4; i++) { rA[i] = unpack2(accA[i]); rB[i] = unpack2(accB[i]); }
            *((float4*)(A.xp_agg + (size_t)d * 32) + ql * 2) =
                make_float4(rA[0].x*invA + rB[0].x*invB, rA[0].y*invA + rB[0].y*invB,
                            rA[1].x*invA + rB[1].x*invB, rA[1].y*invA + rB[1].y*invB);
            *((float4*)(A.xp_agg + (size_t)d * 32) + ql * 2 + 1) =
                make_float4(rA[2].x*invA + rB[2].x*invB, rA[2].y*invA + rB[2].y*invB,
                            rA[3].x*invA + rB[3].x*invB, rA[3].y*invA + rB[3].y*invB);
        }
    } else {
        bool valid = (d < NA_);
        int dd = valid ? d : (NA_ - 1);
        const float* q = A.qa;
        float4 q0 = __ldg((const float4*)(q + (size_t)dd * 32) + ql * 2);
        float4 q1 = __ldg((const float4*)(q + (size_t)dd * 32) + ql * 2 + 1);
        int b0 = __ldg(A.rp_b + dd);
        int b1 = valid ? __ldg(A.rp_b + dd + 1) : b0;
        unsigned long long acc[4];
        acc[0] = acc[1] = acc[2] = acc[3] = pack2(0.f, 0.f);
        float den = accum_rel_h(b0, b1, A.cs_b, A.kv1, q0, q1, gmask, ql, acc);
        if (valid) {
            float inv = (den > 0.f) ? (1.0f / den) : 0.0f;
            float2 a0 = unpack2(acc[0]), a1 = unpack2(acc[1]);
            float2 a2 = unpack2(acc[2]), a3 = unpack2(acc[3]);
            *((float4*)(A.xa_agg + (size_t)d * 32) + ql * 2)     = make_float4(a0.x*inv, a0.y*inv, a1.x*inv, a1.y*inv);
            *((float4*)(A.xa_agg + (size_t)d * 32) + ql * 2 + 1) = make_float4(a2.x*inv, a2.y*inv, a3.x*inv, a3.y*inv);
        }
    }
}

// ---------------- fused output transform ----------------------------------------
// Author blocks [0, ga4) and paper blocks [ga4, ..). Per-part Wa staged in smem.
struct OutArgs {
    const float *x1a, *x1p;
    const float *Wa, *ba;       // authors at +0, papers at +1024 / +32
    const float *skipv;
    const float *xina, *xinp;
    float *outa, *outp;
    __half *out16a, *out16p;    // may be null
    int use_skip;
    int ga4;
};
__global__ void out_all_kernel(OutArgs A) {
    bool isA = (blockIdx.x < (unsigned)A.ga4);
    const float* x1   = isA ? A.x1a : A.x1p;
    const float* Wa   = isA ? A.Wa : (A.Wa + 1024);
    const float* ba   = isA ? A.ba : (A.ba + 32);
    const float* xin  = isA ? A.xina : A.xinp;
    float* out        = isA ? A.outa : A.outp;
    __half* out16     = isA ? A.out16a : A.out16p;
    int t_idx         = isA ? 0 : 1;
    int n             = isA ? NA_ : NP_;
    int blk           = isA ? blockIdx.x : (blockIdx.x - A.ga4);

    __shared__ float sW[1024];
    for (int i = threadIdx.x; i < 1024; i += blockDim.x) sW[i] = Wa[i];
    __syncthreads();
    int lane = threadIdx.x & 31;
    int gw = blk * (blockDim.x >> 5) + (threadIdx.x >> 5);
    int n0 = gw * 4;
    if (n0 >= n) return;
    int m = n - n0; if (m > 4) m = 4;

    float4 xr[4];
#pragma unroll
    for (int j = 0; j < 4; j++) {
        if (j < m && lane < 8) {
            float4 a = __ldg((const float4*)(x1 + (size_t)(n0 + j) * 32) + lane);
            a.x = 0.5f * a.x * (1.0f + erff(a.x * 0.7071067811865475f));
            a.y = 0.5f * a.y * (1.0f + erff(a.y * 0.7071067811865475f));
            a.z = 0.5f * a.z * (1.0f + erff(a.z * 0.7071067811865475f));
            a.w = 0.5f * a.w * (1.0f + erff(a.w * 0.7071067811865475f));
            xr[j] = a;
        } else {
            xr[j] = make_float4(0.f, 0.f, 0.f, 0.f);
        }
    }
    unsigned long long A01 = pack2(ba[lane], ba[lane]), A23 = A01;
    for (int i0 = 0; i0 < 32; i0 += 4) {
        int sl = i0 >> 2;
        float xs[4][4];
#pragma unroll
        for (int j = 0; j < 4; j++) {
            xs[j][0] = __shfl_sync(0xffffffffu, xr[j].x, sl);
            xs[j][1] = __shfl_sync(0xffffffffu, xr[j].y, sl);
            xs[j][2] = __shfl_sync(0xffffffffu, xr[j].z, sl);
            xs[j][3] = __shfl_sync(0xffffffffu, xr[j].w, sl);
        }
#pragma unroll
        for (int c = 0; c < 4; c++) {
            float w = sW[(i0 + c) * 32 + lane];
            unsigned long long w2 = pack2(w, w);
            ffma2(A01, pack2(xs[0][c], xs[1][c]), w2);
            ffma2(A23, pack2(xs[2][c], xs[3][c]), w2);
        }
    }
    float2 a01 = unpack2(A01), a23 = unpack2(A23);
    float o[4] = {a01.x, a01.y, a23.x, a23.y};
    if (A.use_skip) {
        float a = 1.0f / (1.0f + expf(-__ldg(A.skipv + t_idx)));
#pragma unroll
        for (int j = 0; j < 4; j++) {
            if (j < m)
                o[j] = a * o[j] + (1.0f - a) * __ldg(xin + (size_t)(n0 + j) * 32 + lane);
        }
    }
#pragma unroll
    for (int j = 0; j < 4; j++) {
        if (j < m) {
            out[(size_t)(n0 + j) * 32 + lane] = o[j];
            if (out16) {
                out16[(size_t)(n0 + j) * KP2_L2 + lane] = __float2half(o[j]);
                if (lane < 16)
                    out16[(size_t)(n0 + j) * KP2_L2 + 32 + lane] =
                        __float2half(lane == 0 ? 1.0f : 0.0f);
            }
        }
    }
}

// ---------------- host orchestration ----------------------------------------
struct LayerW {
    const float *Wk, *bk, *Wq, *bq, *Wv, *bv, *Wa, *ba, *skip, *arel, *mrel, *prel;
};

template<int KP2, bool F32IN>
static void run_proj(const void* xa_in, const void* xp_in, int F,
                     const LayerW& L,
                     float* qa, float* qp,
                     __half* kv0, __half* kv1, __half* kv2,
                     __half* Wt) {
    const int BT = 256;
    int wsz = F * 32;
    CArgs ca;
    ca.prel = L.prel;
    ca.t[0] = { L.Wq,       L.bq,      (const float*)0, -1 };
    ca.t[1] = { L.Wk,       L.bk,      L.arel + 0,      0  };
    ca.t[2] = { L.Wv,       L.bv,      L.mrel + 0,      -1 };
    ca.t[3] = { L.Wq + wsz, L.bq + 32, (const float*)0, -1 };
    ca.t[4] = { L.Wk + wsz, L.bk + 32, L.arel + 1024,   1  };
    ca.t[5] = { L.Wv + wsz, L.bv + 32, L.mrel + 1024,   -1 };
    ca.t[6] = { L.Wk + wsz, L.bk + 32, L.arel + 2048,   2  };
    ca.t[7] = { L.Wv + wsz, L.bv + 32, L.mrel + 2048,   -1 };
    dim3 cg(divup(KP2 * 32, BT), 8);
    compose_all_kernel<<<cg, BT>>>(ca, F, KP2, Wt);

    proj_wmma_kernel<KP2, 5, F32IN><<<divup(NP_, 128), 256, proj_smem<KP2,5>()>>>(
        xp_in, Wt + (size_t)3 * 32 * KP2, qp,
        kv1, kv1 + 32, kv2, kv2 + 32, NP_);
    proj_wmma_kernel<KP2, 3, F32IN><<<divup(NA_, 128), 256, proj_smem<KP2,3>()>>>(
        xa_in, Wt, qa, kv0, kv0 + 32, (__half*)0, (__half*)0, NA_);
}

static void run_agg_out(const LayerW& L, int use_skip,
                        const float* xa_skip, const float* xp_skip,
                        float* outa, float* outp, __half* outa16, __half* outp16,
                        float* qa, float* qp,
                        __half* kv0, __half* kv1, __half* kv2,
                        float* xa_agg, float* xp_agg,
                        const int* rp_w, const int* cs_w,
                        const int* rp_b, const int* cs_b,
                        const int* rp_c, const int* cs_c) {
    const int BT = 256;
    int gaA = divup(NA_, 64), gpA = divup(NP_, 64);
    AggArgs ag;
    ag.rp_w = rp_w; ag.cs_w = cs_w; ag.rp_c = rp_c; ag.cs_c = cs_c;
    ag.rp_b = rp_b; ag.cs_b = cs_b;
    ag.kv0 = kv0; ag.kv2 = kv2; ag.kv1 = kv1;
    ag.qp = qp; ag.qa = qa;
    ag.xp_agg = xp_agg; ag.xa_agg = xa_agg;
    ag.gpA = gpA;
    agg_all_kernel<<<gpA + gaA, BT>>>(ag);

    int ga4 = divup(NA_, 32), gp4 = divup(NP_, 32);
    OutArgs oa;
    oa.x1a = xa_agg; oa.x1p = xp_agg;
    oa.Wa = L.Wa; oa.ba = L.ba;
    oa.skipv = L.skip;
    oa.xina = xa_skip; oa.xinp = xp_skip;
    oa.outa = outa; oa.outp = outp;
    oa.out16a = outa16; oa.out16p = outp16;
    oa.use_skip = use_skip;
    oa.ga4 = ga4;
    out_all_kernel<<<ga4 + gp4, BT>>>(oa);
}

extern "C" void kernel_launch(void* const* d_in, const int* in_sizes, int n_in,
                              void* d_out, int out_size) {
    const float* x_a   = (const float*)d_in[0];
    const float* x_p   = (const float*)d_in[1];
    const int* e_wr    = (const int*)d_in[2];
    const int* e_wb    = (const int*)d_in[3];
    const int* e_ci    = (const int*)d_in[4];
    LayerW L1 = { (const float*)d_in[5],  (const float*)d_in[6],
                  (const float*)d_in[7],  (const float*)d_in[8],
                  (const float*)d_in[9],  (const float*)d_in[10],
                  (const float*)d_in[11], (const float*)d_in[12],
                  (const float*)d_in[13], (const float*)d_in[14],
                  (const float*)d_in[15], (const float*)d_in[16] };
    LayerW L2 = { (const float*)d_in[17], (const float*)d_in[18],
                  (const float*)d_in[19], (const float*)d_in[20],
                  (const float*)d_in[21], (const float*)d_in[22],
                  (const float*)d_in[23], (const float*)d_in[24],
                  (const float*)d_in[25], (const float*)d_in[26],
                  (const float*)d_in[27], (const float*)d_in[28] };

    float *qa,*qp,*xa_agg,*xp_agg,*h1a,*h1p;
    __half *kv0,*kv1,*kv2,*x16a,*x16p,*Wt;
    cudaGetSymbolAddress((void**)&qa, g_qa);   cudaGetSymbolAddress((void**)&qp, g_qp);
    cudaGetSymbolAddress((void**)&kv0, g_kv0);
    cudaGetSymbolAddress((void**)&kv1, g_kv1);
    cudaGetSymbolAddress((void**)&kv2, g_kv2);
    cudaGetSymbolAddress((void**)&xa_agg, g_xa);
    cudaGetSymbolAddress((void**)&xp_agg, g_xp);
    cudaGetSymbolAddress((void**)&h1a, g_h1a); cudaGetSymbolAddress((void**)&h1p, g_h1p);
    cudaGetSymbolAddress((void**)&x16a, g_x16a); cudaGetSymbolAddress((void**)&x16p, g_x16p);
    cudaGetSymbolAddress((void**)&Wt, g_Wt);

    Rel3 R;
    R.e0 = e_ci; R.E0 = EC_;  R.n0 = NP_;
    R.e1 = e_wr; R.E1 = EW_;  R.n1 = NP_;
    R.e2 = e_wb; R.E2 = EWB_; R.n2 = NA_;
    cudaGetSymbolAddress((void**)&R.deg0, g_deg_c); cudaGetSymbolAddress((void**)&R.rp0, g_rp_c);
    cudaGetSymbolAddress((void**)&R.cs0, g_cs_c);   cudaGetSymbolAddress((void**)&R.bs0, g_bs_c);
    cudaGetSymbolAddress((void**)&R.deg1, g_deg_w); cudaGetSymbolAddress((void**)&R.rp1, g_rp_w);
    cudaGetSymbolAddress((void**)&R.cs1, g_cs_w);   cudaGetSymbolAddress((void**)&R.bs1, g_bs_w);
    cudaGetSymbolAddress((void**)&R.deg2, g_deg_b); cudaGetSymbolAddress((void**)&R.rp2, g_rp_b);
    cudaGetSymbolAddress((void**)&R.cs2, g_cs_b);   cudaGetSymbolAddress((void**)&R.bs2, g_bs_b);

    cudaFuncSetAttribute(proj_wmma_kernel<KP2_L1,3,true>, cudaFuncAttributeMaxDynamicSharedMemorySize,
                         proj_smem<KP2_L1,3>());
    cudaFuncSetAttribute(proj_wmma_kernel<KP2_L1,5,true>, cudaFuncAttributeMaxDynamicSharedMemorySize,
                         proj_smem<KP2_L1,5>());
    cudaFuncSetAttribute(proj_wmma_kernel<KP2_L2,3,false>, cudaFuncAttributeMaxDynamicSharedMemorySize,
                         proj_smem<KP2_L2,3>());
    cudaFuncSetAttribute(proj_wmma_kernel<KP2_L2,5,false>, cudaFuncAttributeMaxDynamicSharedMemorySize,
                         proj_smem<KP2_L2,5>());

    const int BT = 256;
    int totE = EC_ + EW_ + EWB_;
    int totN = NP_ + NP_ + NA_;
    int nbmax = divup(NP_, 1024);

    // Order: zero(1), count(2), compose(3), proj_p(4 <- ncu slot), proj_a,
    //        scans, scatter, fused agg, fused out, layer 2.
    zero_all_kernel<<<divup(totN, BT), BT>>>(R);
    count_all_kernel<<<divup(totE, BT), BT>>>(R);
    run_proj<KP2_L1, true>(x_a, x_p, 128, L1, qa, qp, kv0, kv1, kv2, Wt);

    scan_p1_all<<<dim3(nbmax, 3), 256>>>(R);
    scan_p2_all<<<3, 256>>>(R);
    scan_p3_all<<<dim3(nbmax, 3), 256>>>(R);
    scatter_all_kernel<<<divup(totE, BT), BT>>>(R);

    // Layer 1 agg + out (emits fp16 copy with ones column for layer 2 input)
    run_agg_out(L1, 0, x_a, x_p, h1a, h1p, x16a, x16p,
                qa, qp, kv0, kv1, kv2, xa_agg, xp_agg,
                R.rp1, R.cs1, R.rp2, R.cs2, R.rp0, R.cs0);

    // Layer 2: 32 -> 32, gated skip.
    run_proj<KP2_L2, false>(x16a, x16p, 32, L2, qa, qp, kv0, kv1, kv2, Wt);
    float* out = (float*)d_out;
    run_agg_out(L2, 1, h1a, h1p, out, out + (size_t)NA_ * 32, (__half*)0, (__half*)0,
                qa, qp, kv0, kv1, kv2, xa_agg, xp_agg,
                R.rp1, R.cs1, R.rp2, R.cs2, R.rp0, R.cs0);
}